// round 13
// baseline (speedup 1.0000x reference)
#include <cuda_runtime.h>
#include <math.h>
#include <stdint.h>

#define BB 2
#define TT 2048
#define SS 2048
#define DM 1024
#define NH 16
#define DH 64
#define KK 1024

typedef unsigned long long ull;

// Scratch (static device globals — allocation-free rule)
__device__ float g_qn[(size_t)BB*NH*TT*DH];    // normalized+scaled Q  [b,h,t,d]
__device__ float g_kn[(size_t)BB*NH*SS*DH];    // normalized K         [b,h,s,d]
__device__ float g_vh[(size_t)BB*NH*SS*DH];    // projected V          [b,h,s,d]
__device__ float g_vals[(size_t)BB*TT*DM];     // attention output     [B,T,D]
__device__ float g_biasT[(size_t)NH*TT*SS];    // bias transposed [H,T,S], x log2e

#define LOG2E 1.4426950408889634f
#define FIXC 24.0f

// ---------------- mma.sync tf32 helpers ----------------
__device__ __forceinline__ uint32_t f2tf(float f) {
    uint32_t r; asm("cvt.rna.tf32.f32 %0, %1;" : "=r"(r) : "f"(f)); return r;
}
__device__ __forceinline__ float ex2(float x) {
    float r; asm("ex2.approx.ftz.f32 %0, %1;" : "=f"(r) : "f"(x)); return r;
}
__device__ __forceinline__ void mma8(float* d, const uint32_t* a, const uint32_t* b) {
    asm("mma.sync.aligned.m16n8k8.row.col.f32.tf32.tf32.f32 "
        "{%0,%1,%2,%3}, {%4,%5,%6,%7}, {%8,%9}, {%0,%1,%2,%3};"
        : "+f"(d[0]), "+f"(d[1]), "+f"(d[2]), "+f"(d[3])
        : "r"(a[0]), "r"(a[1]), "r"(a[2]), "r"(a[3]), "r"(b[0]), "r"(b[1]));
}
__device__ __forceinline__ uint32_t s2u(const void* p) {
    uint32_t a;
    asm("{ .reg .u64 t; cvta.to.shared.u64 t, %1; cvt.u32.u64 %0, t; }"
        : "=r"(a) : "l"(p));
    return a;
}
__device__ __forceinline__ void cpa16(uint32_t dst, const void* src) {
    asm volatile("cp.async.cg.shared.global [%0], [%1], 16;"
                 :: "r"(dst), "l"(src) : "memory");
}

// ---------------------------------------------------------------------------
// Tensor-core GEMM body (projections): C = A[4096,1024] * W[1024,1024]^T.
// CTA 128x128, BK=16, 8 warps (2x4), scalar fragment loads.
// ---------------------------------------------------------------------------
#define LDK 20
#define ABUF (128 * LDK)
#define PRE_FLOATS (128 * 132)
#define PRE_SMEM (PRE_FLOATS * (int)sizeof(float))

__device__ __forceinline__ void gemm_mma_body(const float* __restrict__ A,
                                              const float* __restrict__ W,
                                              const float* __restrict__ ls,
                                              int mode, float* sm) {
    float* As = sm;
    float* Bs = sm + 2 * ABUF;
    float* Cs = sm;
    const int m0 = blockIdx.x * 128;
    const int n0 = blockIdx.y * 128;
    const int tid = threadIdx.x;
    const int wid = tid >> 5, lane = tid & 31;
    const int wm = wid >> 2, wn = wid & 3;
    const int g = lane >> 2, tg = lane & 3;

    const int srow = tid >> 1;
    const int skc = (tid & 1) * 8;
    const float* aP = A + (size_t)(m0 + srow) * KK + skc;
    const float* wP = W + (size_t)(n0 + srow) * KK + skc;

    float d[4][4][4];
#pragma unroll
    for (int mt = 0; mt < 4; mt++)
#pragma unroll
        for (int nt = 0; nt < 4; nt++)
#pragma unroll
            for (int r = 0; r < 4; r++) d[mt][nt][r] = 0.f;

    float4 ra0, ra1, rw0, rw1;
    ra0 = *(const float4*)(aP);      ra1 = *(const float4*)(aP + 4);
    rw0 = *(const float4*)(wP);      rw1 = *(const float4*)(wP + 4);

    const int NC = KK / 16;
    for (int c = 0; c < NC; c++) {
        const int buf = c & 1;
        {
            uint32_t* ad = (uint32_t*)(As + buf * ABUF + srow * LDK + skc);
            uint32_t* bd = (uint32_t*)(Bs + buf * ABUF + srow * LDK + skc);
            ad[0] = f2tf(ra0.x); ad[1] = f2tf(ra0.y); ad[2] = f2tf(ra0.z); ad[3] = f2tf(ra0.w);
            ad[4] = f2tf(ra1.x); ad[5] = f2tf(ra1.y); ad[6] = f2tf(ra1.z); ad[7] = f2tf(ra1.w);
            bd[0] = f2tf(rw0.x); bd[1] = f2tf(rw0.y); bd[2] = f2tf(rw0.z); bd[3] = f2tf(rw0.w);
            bd[4] = f2tf(rw1.x); bd[5] = f2tf(rw1.y); bd[6] = f2tf(rw1.z); bd[7] = f2tf(rw1.w);
        }
        __syncthreads();
        if (c + 1 < NC) {
            int ko = (c + 1) * 16;
            ra0 = *(const float4*)(aP + ko);  ra1 = *(const float4*)(aP + ko + 4);
            rw0 = *(const float4*)(wP + ko);  rw1 = *(const float4*)(wP + ko + 4);
        }
        const uint32_t* Ab = (const uint32_t*)(As + buf * ABUF);
        const uint32_t* Bb = (const uint32_t*)(Bs + buf * ABUF);
#pragma unroll
        for (int ks = 0; ks < 2; ks++) {
            const int k = ks * 8 + tg;
            uint32_t af[4][4], bf[4][2];
#pragma unroll
            for (int mt = 0; mt < 4; mt++) {
                int r = wm * 64 + mt * 16 + g;
                af[mt][0] = Ab[r * LDK + k];
                af[mt][1] = Ab[(r + 8) * LDK + k];
                af[mt][2] = Ab[r * LDK + k + 4];
                af[mt][3] = Ab[(r + 8) * LDK + k + 4];
            }
#pragma unroll
            for (int nt = 0; nt < 4; nt++) {
                int n = wn * 32 + nt * 8 + g;
                bf[nt][0] = Bb[n * LDK + k];
                bf[nt][1] = Bb[n * LDK + k + 4];
            }
#pragma unroll
            for (int mt = 0; mt < 4; mt++)
#pragma unroll
                for (int nt = 0; nt < 4; nt++)
                    mma8(d[mt][nt], af[mt], bf[nt]);
        }
        __syncthreads();
    }

#pragma unroll
    for (int mt = 0; mt < 4; mt++) {
        int r = wm * 64 + mt * 16 + g;
#pragma unroll
        for (int nt = 0; nt < 4; nt++) {
            int cc = wn * 32 + nt * 8 + 2 * tg;
            *(float2*)&Cs[r * 132 + cc]       = make_float2(d[mt][nt][0], d[mt][nt][1]);
            *(float2*)&Cs[(r + 8) * 132 + cc] = make_float2(d[mt][nt][2], d[mt][nt][3]);
        }
    }
    __syncthreads();

    {
        const int row = tid >> 1;
        const int half = tid & 1;
        float f[64];
        const float* src = &Cs[row * 132 + half * 64];
#pragma unroll
        for (int j = 0; j < 16; j++) {
            float4 v = *(const float4*)(src + j * 4);
            f[4 * j] = v.x; f[4 * j + 1] = v.y; f[4 * j + 2] = v.z; f[4 * j + 3] = v.w;
        }
        {
            float ssq = 0.f;
#pragma unroll
            for (int j = 0; j < 64; j++) ssq += f[j] * f[j];
            float hs = 1.0f;
            if (mode == 3)   // fold log2e into Q's logit scale (log2-domain softmax)
                hs = expf(fminf(ls[blockIdx.y * 2 + half], 4.6051701859880914f)) * LOG2E;
            float inv = hs / fmaxf(sqrtf(ssq), 1e-12f);
            if (mode >= 2)
#pragma unroll
                for (int j = 0; j < 64; j++) f[j] *= inv;
        }
        const int m = m0 + row;
        int b = m >> 11, t = m & 2047;
        int h = (n0 >> 6) + half;
        float* base = (mode == 1) ? g_vh : (mode == 2) ? g_kn : g_qn;
        float* dst = base + (((size_t)(b * NH + h)) * TT + t) * DH;
#pragma unroll
        for (int j = 0; j < 16; j++)
            *(float4*)(dst + j * 4) =
                make_float4(f[4 * j], f[4 * j + 1], f[4 * j + 2], f[4 * j + 3]);
    }
}

// ---------------------------------------------------------------------------
// Output GEMM body: 64x128 tile (wave-balance), warp grid 2x4, warp tile 32x32.
// A = g_vals [4096,1024], W = Wout, out plain [4096,1024]. No norm.
// Smem: As[2][64*20]=2560 | Bs[2][128*20]=5120 ; Cs overlay [64][132]=8448.
// ---------------------------------------------------------------------------
#define ABUF_A64 (64 * LDK)

__global__ __launch_bounds__(256, 2) void gemm_out_kernel(const float* __restrict__ W,
                                                          float* __restrict__ out) {
    extern __shared__ float sm[];
    float* As = sm;                       // [2][1280]
    float* Bs = sm + 2 * ABUF_A64;        // [2][2560]
    float* Cs = sm;                       // overlay [64][132]
    const float* A = (const float*)g_vals;
    const int m0 = blockIdx.x * 64;
    const int n0 = blockIdx.y * 128;
    const int tid = threadIdx.x;
    const int wid = tid >> 5, lane = tid & 31;
    const int wm = wid >> 2, wn = wid & 3;
    const int g = lane >> 2, tg = lane & 3;

    // staging: A rows 64 (one float4/thread), B rows 128 (two float4/thread)
    const int arow = tid & 63;
    const int akc = (tid >> 6) * 4;
    const int brow = tid >> 1;
    const int bkc = (tid & 1) * 8;
    const float* aP = A + (size_t)(m0 + arow) * KK + akc;
    const float* wP = W + (size_t)(n0 + brow) * KK + bkc;

    float d[2][4][4];
#pragma unroll
    for (int mt = 0; mt < 2; mt++)
#pragma unroll
        for (int nt = 0; nt < 4; nt++)
#pragma unroll
            for (int r = 0; r < 4; r++) d[mt][nt][r] = 0.f;

    float4 ra, rw0, rw1;
    ra = *(const float4*)(aP);
    rw0 = *(const float4*)(wP);  rw1 = *(const float4*)(wP + 4);

    const int NC = KK / 16;
    for (int c = 0; c < NC; c++) {
        const int buf = c & 1;
        {
            uint32_t* ad = (uint32_t*)(As + buf * ABUF_A64 + arow * LDK + akc);
            uint32_t* bd = (uint32_t*)(Bs + buf * ABUF + brow * LDK + bkc);
            ad[0] = f2tf(ra.x); ad[1] = f2tf(ra.y); ad[2] = f2tf(ra.z); ad[3] = f2tf(ra.w);
            bd[0] = f2tf(rw0.x); bd[1] = f2tf(rw0.y); bd[2] = f2tf(rw0.z); bd[3] = f2tf(rw0.w);
            bd[4] = f2tf(rw1.x); bd[5] = f2tf(rw1.y); bd[6] = f2tf(rw1.z); bd[7] = f2tf(rw1.w);
        }
        __syncthreads();
        if (c + 1 < NC) {
            int ko = (c + 1) * 16;
            ra = *(const float4*)(aP + ko);
            rw0 = *(const float4*)(wP + ko);  rw1 = *(const float4*)(wP + ko + 4);
        }
        const uint32_t* Ab = (const uint32_t*)(As + buf * ABUF_A64);
        const uint32_t* Bb = (const uint32_t*)(Bs + buf * ABUF);
#pragma unroll
        for (int ks = 0; ks < 2; ks++) {
            const int k = ks * 8 + tg;
            uint32_t af[2][4], bf[4][2];
#pragma unroll
            for (int mt = 0; mt < 2; mt++) {
                int r = wm * 32 + mt * 16 + g;
                af[mt][0] = Ab[r * LDK + k];
                af[mt][1] = Ab[(r + 8) * LDK + k];
                af[mt][2] = Ab[r * LDK + k + 4];
                af[mt][3] = Ab[(r + 8) * LDK + k + 4];
            }
#pragma unroll
            for (int nt = 0; nt < 4; nt++) {
                int n = wn * 32 + nt * 8 + g;
                bf[nt][0] = Bb[n * LDK + k];
                bf[nt][1] = Bb[n * LDK + k + 4];
            }
#pragma unroll
            for (int mt = 0; mt < 2; mt++)
#pragma unroll
                for (int nt = 0; nt < 4; nt++)
                    mma8(d[mt][nt], af[mt], bf[nt]);
        }
        __syncthreads();
    }

#pragma unroll
    for (int mt = 0; mt < 2; mt++) {
        int r = wm * 32 + mt * 16 + g;
#pragma unroll
        for (int nt = 0; nt < 4; nt++) {
            int cc = wn * 32 + nt * 8 + 2 * tg;
            *(float2*)&Cs[r * 132 + cc]       = make_float2(d[mt][nt][0], d[mt][nt][1]);
            *(float2*)&Cs[(r + 8) * 132 + cc] = make_float2(d[mt][nt][2], d[mt][nt][3]);
        }
    }
    __syncthreads();

    {
        const int row = tid >> 2;          // 0..63
        const int q = tid & 3;             // 32-col quarter
        const float* src = &Cs[row * 132 + q * 32];
        float* dst = out + (size_t)(m0 + row) * DM + n0 + q * 32;
#pragma unroll
        for (int j = 0; j < 8; j++)
            *(float4*)(dst + j * 4) = *(const float4*)(src + j * 4);
    }
}

// ---------------------------------------------------------------------------
// Bias transpose: [T,S,H] -> [H,T,S], scaled by log2e.
// ---------------------------------------------------------------------------
__device__ __forceinline__ void transpose_body(const float* __restrict__ in, float* sm) {
    const int c = blockIdx.y * 32 + blockIdx.x;
    const int tid = threadIdx.x;
    for (int tb = 0; tb < 2; tb++) {
        const int t0 = (c * 2 + tb) * 4;
        for (int s0 = 0; s0 < SS; s0 += 64) {
#pragma unroll
            for (int tt = 0; tt < 4; tt++) {
                const float* src = in + ((size_t)(t0 + tt) * SS + s0) * NH;
#pragma unroll
                for (int p = 0; p < 4; p++) {
                    int idx = p * 256 + tid;
                    int h = idx & 15, ss = idx >> 4;
                    sm[h * 261 + tt * 64 + ss] = src[idx] * LOG2E;
                }
            }
            __syncthreads();
#pragma unroll
            for (int p = 0; p < 16; p++) {
                int idx = p * 256 + tid;
                int ss = idx & 63;
                int combo = idx >> 6;
                int tt = combo & 3, h = combo >> 2;
                g_biasT[(size_t)h * TT * SS + (size_t)(t0 + tt) * SS + s0 + ss] =
                    sm[h * 261 + tt * 64 + ss];
            }
            __syncthreads();
        }
    }
}

__global__ __launch_bounds__(256, 2) void fused_pre_kernel(const float* __restrict__ q,
                                                           const float* __restrict__ k,
                                                           const float* __restrict__ v,
                                                           const float* __restrict__ bias,
                                                           const float* __restrict__ Wqkv,
                                                           const float* __restrict__ ls) {
    extern __shared__ float sm[];
    const int z = blockIdx.z;
    if (z == 0)      gemm_mma_body(q, Wqkv, ls, 3, sm);
    else if (z == 1) gemm_mma_body(k, Wqkv, nullptr, 2, sm);
    else if (z == 2) gemm_mma_body(v, Wqkv, nullptr, 1, sm);
    else             transpose_body(bias, sm);
}

// ---------------------------------------------------------------------------
// Flash attention (R11-verbatim): BM=128(t), BN=64(s), 256 thr, 8 warps 4x2.
// Smem: Qs[128][68] | Ks[64][68] | Vt[64][68] | Ps[128][68] | Ls[2][128].
// ---------------------------------------------------------------------------
#define W68 68
#define ATT_FLOATS (128*W68 + 64*W68 + 64*W68 + 128*W68 + 256)
#define ATT_SMEM (ATT_FLOATS * (int)sizeof(float))

__global__ __launch_bounds__(256, 2) void attention_kernel() {
    extern __shared__ float sm[];
    float* Qs = sm;                         // [128][68] tf32 bits
    float* Ks = sm + 128 * W68;             // [64][68] tf32 bits
    float* Vt = Ks + 64 * W68;              // [64][68] tf32 bits (dh-major)
    float* Ps = Vt + 64 * W68;              // [128][68]  (bias, then P)
    float* Ls = Ps + 128 * W68;             // [2][128]

    const int t0 = blockIdx.x * 128;
    const int h = blockIdx.y;
    const int b = blockIdx.z;
    const int tid = threadIdx.x;
    const int tx = tid & 15, ty = tid >> 4;
    const int wid = tid >> 5, lane = tid & 31;
    const int g = lane >> 2, tg = lane & 3;
    const int wm = wid >> 1, wn = wid & 1;   // 4 x 2 warp grid

    const uint32_t ps_u = s2u(Ps);

    const float* qptr  = g_qn + (((size_t)(b * NH + h)) * TT + t0) * DH;
    const float* kbase = g_kn + ((size_t)(b * NH + h)) * SS * DH;
    const float* vbase = g_vh + ((size_t)(b * NH + h)) * SS * DH;
    const float* bptr  = g_biasT + (size_t)h * TT * SS + (size_t)t0 * SS;

    // Stage Q tile once: natural [m][d] layout, tf32 bits
    {
        int row = tid >> 1;
        int dc0 = (tid & 1) * 32;
        const float* qp = qptr + (size_t)row * DH + dc0;
        uint32_t* Qb = (uint32_t*)Qs;
#pragma unroll
        for (int j = 0; j < 8; j++) {
            float4 v = *(const float4*)(qp + j * 4);
            int c = dc0 + j * 4;
            Qb[row * W68 + c + 0] = f2tf(v.x);
            Qb[row * W68 + c + 1] = f2tf(v.y);
            Qb[row * W68 + c + 2] = f2tf(v.z);
            Qb[row * W68 + c + 3] = f2tf(v.w);
        }
    }

    float lsum[4] = {0.f, 0.f, 0.f, 0.f};
    float o[2][4][4];
#pragma unroll
    for (int mt = 0; mt < 2; mt++)
#pragma unroll
        for (int nt = 0; nt < 4; nt++)
#pragma unroll
            for (int r = 0; r < 4; r++) o[mt][nt][r] = 0.f;

    for (int s0 = 0; s0 < SS; s0 += 64) {
        __syncthreads();   // prev-iter readers of Ks/Vt/Ps done

        // prefetch this tile's bias into Ps via cp.async
#pragma unroll
        for (int i = 0; i < 8; i++) {
            uint32_t dst = ps_u + (uint32_t)(((ty * 8 + i) * W68 + tx * 4) * 4);
            cpa16(dst, bptr + (size_t)(ty * 8 + i) * SS + s0 + tx * 4);
        }
        asm volatile("cp.async.commit_group;" ::: "memory");

        // stage K (natural [s][d]) and V (dh-major [d][s]) as tf32
        {
            int s = tid >> 2;
            int dc = (tid & 3) * 16;
            const float* kp = kbase + (size_t)(s0 + s) * DH + dc;
            const float* vp = vbase + (size_t)(s0 + s) * DH + dc;
            uint32_t* Kb = (uint32_t*)Ks;
            uint32_t* Vb = (uint32_t*)Vt;
#pragma unroll
            for (int q = 0; q < 4; q++) {
                float4 kv = *(const float4*)(kp + q * 4);
                int d = dc + q * 4;
                Kb[s * W68 + d + 0] = f2tf(kv.x);
                Kb[s * W68 + d + 1] = f2tf(kv.y);
                Kb[s * W68 + d + 2] = f2tf(kv.z);
                Kb[s * W68 + d + 3] = f2tf(kv.w);
            }
#pragma unroll
            for (int q = 0; q < 4; q++) {
                float4 vv = *(const float4*)(vp + q * 4);
                int d = dc + q * 4;
                Vb[(d + 0) * W68 + s] = f2tf(vv.x);
                Vb[(d + 1) * W68 + s] = f2tf(vv.y);
                Vb[(d + 2) * W68 + s] = f2tf(vv.z);
                Vb[(d + 3) * W68 + s] = f2tf(vv.w);
            }
        }
        __syncthreads();

        // S = Q K^T via mma.sync tf32 (warp tile 32m x 32n, K-dim 64)
        float sf[2][4][4];
#pragma unroll
        for (int mt = 0; mt < 2; mt++)
#pragma unroll
            for (int nt = 0; nt < 4; nt++)
#pragma unroll
                for (int r = 0; r < 4; r++) sf[mt][nt][r] = 0.f;
        {
            const uint32_t* Qb = (const uint32_t*)Qs;
            const uint32_t* Kb = (const uint32_t*)Ks;
#pragma unroll
            for (int k8 = 0; k8 < 8; k8++) {
                const int k = k8 * 8 + tg;
                uint32_t af[2][4], bf[4][2];
#pragma unroll
                for (int mt = 0; mt < 2; mt++) {
                    int r = wm * 32 + mt * 16 + g;
                    af[mt][0] = Qb[r * W68 + k];
                    af[mt][1] = Qb[(r + 8) * W68 + k];
                    af[mt][2] = Qb[r * W68 + k + 4];
                    af[mt][3] = Qb[(r + 8) * W68 + k + 4];
                }
#pragma unroll
                for (int nt = 0; nt < 4; nt++) {
                    int n = wn * 32 + nt * 8 + g;
                    bf[nt][0] = Kb[n * W68 + k];
                    bf[nt][1] = Kb[n * W68 + k + 4];
                }
#pragma unroll
                for (int mt = 0; mt < 2; mt++)
#pragma unroll
                    for (int nt = 0; nt < 4; nt++)
                        mma8(sf[mt][nt], af[mt], bf[nt]);
            }
        }

        // bias (prefetched) + ex2 in fragment layout; write P into Ps
        asm volatile("cp.async.wait_group 0;" ::: "memory");
        __syncthreads();
#pragma unroll
        for (int mt = 0; mt < 2; mt++) {
            int r0 = wm * 32 + mt * 16 + g;
#pragma unroll
            for (int nt = 0; nt < 4; nt++) {
                int c = wn * 32 + nt * 8 + 2 * tg;
                float2 b0 = *(float2*)&Ps[r0 * W68 + c];
                float2 b1 = *(float2*)&Ps[(r0 + 8) * W68 + c];
                float p00 = ex2(sf[mt][nt][0] + b0.x - FIXC);
                float p01 = ex2(sf[mt][nt][1] + b0.y - FIXC);
                float p10 = ex2(sf[mt][nt][2] + b1.x - FIXC);
                float p11 = ex2(sf[mt][nt][3] + b1.y - FIXC);
                lsum[mt * 2 + 0] += p00 + p01;
                lsum[mt * 2 + 1] += p10 + p11;
                *(float2*)&Ps[r0 * W68 + c]       = make_float2(p00, p01);
                *(float2*)&Ps[(r0 + 8) * W68 + c] = make_float2(p10, p11);
            }
        }
        __syncthreads();

        // O += P V (mma.sync tf32; P raw fp32, HW-truncated)
        {
            const uint32_t* Pr = (const uint32_t*)Ps;
            const uint32_t* Vr = (const uint32_t*)Vt;
#pragma unroll
            for (int kk = 0; kk < 8; kk++) {
                const int k = kk * 8 + tg;
                uint32_t af[2][4];
#pragma unroll
                for (int mt = 0; mt < 2; mt++) {
                    int r = wm * 32 + mt * 16 + g;
                    af[mt][0] = Pr[r * W68 + k];
                    af[mt][1] = Pr[(r + 8) * W68 + k];
                    af[mt][2] = Pr[r * W68 + k + 4];
                    af[mt][3] = Pr[(r + 8) * W68 + k + 4];
                }
#pragma unroll
                for (int nt = 0; nt < 4; nt++) {
                    int n = wn * 32 + nt * 8 + g;
                    uint32_t bf[2];
                    bf[0] = Vr[n * W68 + k];
                    bf[1] = Vr[n * W68 + k + 4];
                    mma8(o[0][nt], af[0], bf);
                    mma8(o[1][nt], af[1], bf);
                }
            }
        }
    }

    // reduce lsum over the 4-lane tg group; publish per-row, per-wn sums
#pragma unroll
    for (int i = 0; i < 4; i++) {
        lsum[i] += __shfl_xor_sync(0xffffffffu, lsum[i], 1);
        lsum[i] += __shfl_xor_sync(0xffffffffu, lsum[i], 2);
    }
    if (tg == 0) {
#pragma unroll
        for (int mt = 0; mt < 2; mt++) {
            int r = wm * 32 + mt * 16 + g;
            Ls[wn * 128 + r]     = lsum[mt * 2 + 0];
            Ls[wn * 128 + r + 8] = lsum[mt * 2 + 1];
        }
    }
    __syncthreads();

    // epilogue: normalize O fragments and write to g_vals [B,T,D]
#pragma unroll
    for (int mt = 0; mt < 2; mt++) {
        int r = wm * 32 + mt * 16 + g;
        float inv0 = 1.0f / (Ls[r] + Ls[128 + r]);
        float inv1 = 1.0f / (Ls[r + 8] + Ls[128 + r + 8]);
        float* d0 = g_vals + ((size_t)(b * TT) + t0 + r) * DM + h * DH;
        float* d1 = g_vals + ((size_t)(b * TT) + t0 + r + 8) * DM + h * DH;
#pragma unroll
        for (int nt = 0; nt < 4; nt++) {
            int c = wn * 32 + nt * 8 + 2 * tg;
            *(float2*)(d0 + c) = make_float2(o[mt][nt][0] * inv0, o[mt][nt][1] * inv0);
            *(float2*)(d1 + c) = make_float2(o[mt][nt][2] * inv1, o[mt][nt][3] * inv1);
        }
    }
}

// ---------------------------------------------------------------------------
extern "C" void kernel_launch(void* const* d_in, const int* in_sizes, int n_in,
                              void* d_out, int out_size) {
    const float* q    = (const float*)d_in[0];
    const float* k    = (const float*)d_in[1];
    const float* v    = (const float*)d_in[2];
    const float* bias = (const float*)d_in[3];
    const float* Wqkv = (const float*)d_in[4];
    const float* Wout = (const float*)d_in[5];
    const float* ls   = (const float*)d_in[6];
    float* out = (float*)d_out;

    cudaFuncSetAttribute(attention_kernel,
                         cudaFuncAttributeMaxDynamicSharedMemorySize, ATT_SMEM);
    cudaFuncSetAttribute(fused_pre_kernel,
                         cudaFuncAttributeMaxDynamicSharedMemorySize, PRE_SMEM);
    cudaFuncSetAttribute(gemm_out_kernel,
                         cudaFuncAttributeMaxDynamicSharedMemorySize, PRE_SMEM);

    fused_pre_kernel<<<dim3(32, 8, 4), 256, PRE_SMEM>>>(q, k, v, bias, Wqkv, ls);

    attention_kernel<<<dim3(TT / 128, NH, BB), 256, ATT_SMEM>>>();

    gemm_out_kernel<<<dim3(64, 8), 256, PRE_SMEM>>>(Wout, out);
}

// round 14
// speedup vs baseline: 1.1018x; 1.1018x over previous
#include <cuda_runtime.h>
#include <math.h>
#include <stdint.h>

#define BB 2
#define TT 2048
#define SS 2048
#define DM 1024
#define NH 16
#define DH 64
#define KK 1024

typedef unsigned long long ull;

// Scratch (static device globals — allocation-free rule)
// NOTE: g_qn/g_kn/g_vh hold TF32 BIT PATTERNS (uint32), written by the
// projection epilogue; attention consumes them directly via cp.async/LDG.
__device__ float g_qn[(size_t)BB*NH*TT*DH];
__device__ float g_kn[(size_t)BB*NH*SS*DH];
__device__ float g_vh[(size_t)BB*NH*SS*DH];
__device__ float g_vals[(size_t)BB*TT*DM];     // attention output [B,T,D] (fp32)
__device__ float g_biasT[(size_t)NH*TT*SS];    // bias transposed [H,T,S], x log2e

#define LOG2E 1.4426950408889634f
#define FIXC 24.0f

// ---------------- mma.sync tf32 helpers ----------------
__device__ __forceinline__ uint32_t f2tf(float f) {
    uint32_t r; asm("cvt.rna.tf32.f32 %0, %1;" : "=r"(r) : "f"(f)); return r;
}
__device__ __forceinline__ float ex2(float x) {
    float r; asm("ex2.approx.ftz.f32 %0, %1;" : "=f"(r) : "f"(x)); return r;
}
__device__ __forceinline__ void mma8(float* d, const uint32_t* a, const uint32_t* b) {
    asm("mma.sync.aligned.m16n8k8.row.col.f32.tf32.tf32.f32 "
        "{%0,%1,%2,%3}, {%4,%5,%6,%7}, {%8,%9}, {%0,%1,%2,%3};"
        : "+f"(d[0]), "+f"(d[1]), "+f"(d[2]), "+f"(d[3])
        : "r"(a[0]), "r"(a[1]), "r"(a[2]), "r"(a[3]), "r"(b[0]), "r"(b[1]));
}
__device__ __forceinline__ uint32_t s2u(const void* p) {
    uint32_t a;
    asm("{ .reg .u64 t; cvta.to.shared.u64 t, %1; cvt.u32.u64 %0, t; }"
        : "=r"(a) : "l"(p));
    return a;
}
__device__ __forceinline__ void cpa16(uint32_t dst, const void* src) {
    asm volatile("cp.async.cg.shared.global [%0], [%1], 16;"
                 :: "r"(dst), "l"(src) : "memory");
}

// ---------------------------------------------------------------------------
// Tensor-core GEMM body: C = A[4096,1024] * W[1024,1024]^T.
// CTA 128x128, BK=16, 8 warps (2x4), scalar fragment loads.
// mode 0: fp32 -> dst_plain   mode 1/2/3: TF32 BITS -> g_vh/g_kn/g_qn
// ---------------------------------------------------------------------------
#define LDK 20
#define ABUF (128 * LDK)
#define PRE_FLOATS (128 * 132)
#define PRE_SMEM (PRE_FLOATS * (int)sizeof(float))

__device__ __forceinline__ void gemm_mma_body(const float* __restrict__ A,
                                              const float* __restrict__ W,
                                              float* __restrict__ dst_plain,
                                              const float* __restrict__ ls,
                                              int mode, float* sm) {
    float* As = sm;
    float* Bs = sm + 2 * ABUF;
    float* Cs = sm;
    const int m0 = blockIdx.x * 128;
    const int n0 = blockIdx.y * 128;
    const int tid = threadIdx.x;
    const int wid = tid >> 5, lane = tid & 31;
    const int wm = wid >> 2, wn = wid & 3;
    const int g = lane >> 2, tg = lane & 3;

    const int srow = tid >> 1;
    const int skc = (tid & 1) * 8;
    const float* aP = A + (size_t)(m0 + srow) * KK + skc;
    const float* wP = W + (size_t)(n0 + srow) * KK + skc;

    float d[4][4][4];
#pragma unroll
    for (int mt = 0; mt < 4; mt++)
#pragma unroll
        for (int nt = 0; nt < 4; nt++)
#pragma unroll
            for (int r = 0; r < 4; r++) d[mt][nt][r] = 0.f;

    float4 ra0, ra1, rw0, rw1;
    ra0 = *(const float4*)(aP);      ra1 = *(const float4*)(aP + 4);
    rw0 = *(const float4*)(wP);      rw1 = *(const float4*)(wP + 4);

    const int NC = KK / 16;
    for (int c = 0; c < NC; c++) {
        const int buf = c & 1;
        {
            uint32_t* ad = (uint32_t*)(As + buf * ABUF + srow * LDK + skc);
            uint32_t* bd = (uint32_t*)(Bs + buf * ABUF + srow * LDK + skc);
            ad[0] = f2tf(ra0.x); ad[1] = f2tf(ra0.y); ad[2] = f2tf(ra0.z); ad[3] = f2tf(ra0.w);
            ad[4] = f2tf(ra1.x); ad[5] = f2tf(ra1.y); ad[6] = f2tf(ra1.z); ad[7] = f2tf(ra1.w);
            bd[0] = f2tf(rw0.x); bd[1] = f2tf(rw0.y); bd[2] = f2tf(rw0.z); bd[3] = f2tf(rw0.w);
            bd[4] = f2tf(rw1.x); bd[5] = f2tf(rw1.y); bd[6] = f2tf(rw1.z); bd[7] = f2tf(rw1.w);
        }
        __syncthreads();
        if (c + 1 < NC) {
            int ko = (c + 1) * 16;
            ra0 = *(const float4*)(aP + ko);  ra1 = *(const float4*)(aP + ko + 4);
            rw0 = *(const float4*)(wP + ko);  rw1 = *(const float4*)(wP + ko + 4);
        }
        const uint32_t* Ab = (const uint32_t*)(As + buf * ABUF);
        const uint32_t* Bb = (const uint32_t*)(Bs + buf * ABUF);
#pragma unroll
        for (int ks = 0; ks < 2; ks++) {
            const int k = ks * 8 + tg;
            uint32_t af[4][4], bf[4][2];
#pragma unroll
            for (int mt = 0; mt < 4; mt++) {
                int r = wm * 64 + mt * 16 + g;
                af[mt][0] = Ab[r * LDK + k];
                af[mt][1] = Ab[(r + 8) * LDK + k];
                af[mt][2] = Ab[r * LDK + k + 4];
                af[mt][3] = Ab[(r + 8) * LDK + k + 4];
            }
#pragma unroll
            for (int nt = 0; nt < 4; nt++) {
                int n = wn * 32 + nt * 8 + g;
                bf[nt][0] = Bb[n * LDK + k];
                bf[nt][1] = Bb[n * LDK + k + 4];
            }
#pragma unroll
            for (int mt = 0; mt < 4; mt++)
#pragma unroll
                for (int nt = 0; nt < 4; nt++)
                    mma8(d[mt][nt], af[mt], bf[nt]);
        }
        __syncthreads();
    }

#pragma unroll
    for (int mt = 0; mt < 4; mt++) {
        int r = wm * 64 + mt * 16 + g;
#pragma unroll
        for (int nt = 0; nt < 4; nt++) {
            int cc = wn * 32 + nt * 8 + 2 * tg;
            *(float2*)&Cs[r * 132 + cc]       = make_float2(d[mt][nt][0], d[mt][nt][1]);
            *(float2*)&Cs[(r + 8) * 132 + cc] = make_float2(d[mt][nt][2], d[mt][nt][3]);
        }
    }
    __syncthreads();

    {
        const int row = tid >> 1;
        const int half = tid & 1;
        float f[64];
        const float* src = &Cs[row * 132 + half * 64];
#pragma unroll
        for (int j = 0; j < 16; j++) {
            float4 v = *(const float4*)(src + j * 4);
            f[4 * j] = v.x; f[4 * j + 1] = v.y; f[4 * j + 2] = v.z; f[4 * j + 3] = v.w;
        }
        if (mode >= 2) {
            float ssq = 0.f;
#pragma unroll
            for (int j = 0; j < 64; j++) ssq += f[j] * f[j];
            float hs = 1.0f;
            if (mode == 3)   // fold log2e into Q's logit scale (log2-domain softmax)
                hs = expf(fminf(ls[blockIdx.y * 2 + half], 4.6051701859880914f)) * LOG2E;
            float inv = hs / fmaxf(sqrtf(ssq), 1e-12f);
#pragma unroll
            for (int j = 0; j < 64; j++) f[j] *= inv;
        }
        const int m = m0 + row;
        if (mode == 0) {
            float* dst = dst_plain + (size_t)m * DM + n0 + half * 64;
#pragma unroll
            for (int j = 0; j < 16; j++)
                *(float4*)(dst + j * 4) =
                    make_float4(f[4 * j], f[4 * j + 1], f[4 * j + 2], f[4 * j + 3]);
        } else {
            // store TF32 BIT PATTERNS (consumed directly by attention mma)
            int b = m >> 11, t = m & 2047;
            int h = (n0 >> 6) + half;
            float* base = (mode == 1) ? g_vh : (mode == 2) ? g_kn : g_qn;
            uint32_t* dst = (uint32_t*)(base + (((size_t)(b * NH + h)) * TT + t) * DH);
#pragma unroll
            for (int j = 0; j < 16; j++) {
                uint4 u;
                u.x = f2tf(f[4 * j]);
                u.y = f2tf(f[4 * j + 1]);
                u.z = f2tf(f[4 * j + 2]);
                u.w = f2tf(f[4 * j + 3]);
                *(uint4*)(dst + j * 4) = u;
            }
        }
    }
}

// ---------------------------------------------------------------------------
// Bias transpose: [T,S,H] -> [H,T,S], scaled by log2e.
// ---------------------------------------------------------------------------
__device__ __forceinline__ void transpose_body(const float* __restrict__ in, float* sm) {
    const int c = blockIdx.y * 32 + blockIdx.x;
    const int tid = threadIdx.x;
    for (int tb = 0; tb < 2; tb++) {
        const int t0 = (c * 2 + tb) * 4;
        for (int s0 = 0; s0 < SS; s0 += 64) {
#pragma unroll
            for (int tt = 0; tt < 4; tt++) {
                const float* src = in + ((size_t)(t0 + tt) * SS + s0) * NH;
#pragma unroll
                for (int p = 0; p < 4; p++) {
                    int idx = p * 256 + tid;
                    int h = idx & 15, ss = idx >> 4;
                    sm[h * 261 + tt * 64 + ss] = src[idx] * LOG2E;
                }
            }
            __syncthreads();
#pragma unroll
            for (int p = 0; p < 16; p++) {
                int idx = p * 256 + tid;
                int ss = idx & 63;
                int combo = idx >> 6;
                int tt = combo & 3, h = combo >> 2;
                g_biasT[(size_t)h * TT * SS + (size_t)(t0 + tt) * SS + s0 + ss] =
                    sm[h * 261 + tt * 64 + ss];
            }
            __syncthreads();
        }
    }
}

__global__ __launch_bounds__(256, 2) void fused_pre_kernel(const float* __restrict__ q,
                                                           const float* __restrict__ k,
                                                           const float* __restrict__ v,
                                                           const float* __restrict__ bias,
                                                           const float* __restrict__ Wqkv,
                                                           const float* __restrict__ ls) {
    extern __shared__ float sm[];
    const int z = blockIdx.z;
    if (z == 0)      gemm_mma_body(q, Wqkv, nullptr, ls, 3, sm);
    else if (z == 1) gemm_mma_body(k, Wqkv, nullptr, nullptr, 2, sm);
    else if (z == 2) gemm_mma_body(v, Wqkv, nullptr, nullptr, 1, sm);
    else             transpose_body(bias, sm);
}

__global__ __launch_bounds__(256, 2) void gemm_out_kernel(const float* __restrict__ Wout,
                                                          float* __restrict__ out) {
    extern __shared__ float sm[];
    gemm_mma_body((const float*)g_vals, Wout, out, nullptr, 0, sm);
}

// ---------------------------------------------------------------------------
// Flash attention v5: BM=128(t), BN=64(s), 256 thr, 8 warps 4x2, all-tensor.
// Q/K staged via cp.async (tf32 bits already in gmem — zero cvt, zero regs).
// V: uint4 LDG + transpose STS (no cvt). Bias via cp.async into Ps.
// Smem: Qs[128][68] | Ks[64][68] | Vt[64][68] | Ps[128][68] | Ls[2][128].
// ---------------------------------------------------------------------------
#define W68 68
#define ATT_FLOATS (128*W68 + 64*W68 + 64*W68 + 128*W68 + 256)
#define ATT_SMEM (ATT_FLOATS * (int)sizeof(float))

__global__ __launch_bounds__(256, 2) void attention_kernel() {
    extern __shared__ float sm[];
    float* Qs = sm;                         // [128][68] tf32 bits
    float* Ks = sm + 128 * W68;             // [64][68] tf32 bits
    float* Vt = Ks + 64 * W68;              // [64][68] tf32 bits (dh-major)
    float* Ps = Vt + 64 * W68;              // [128][68]  (bias, then P)
    float* Ls = Ps + 128 * W68;             // [2][128]

    const int t0 = blockIdx.x * 128;
    const int h = blockIdx.y;
    const int b = blockIdx.z;
    const int tid = threadIdx.x;
    const int tx = tid & 15, ty = tid >> 4;
    const int wid = tid >> 5, lane = tid & 31;
    const int g = lane >> 2, tg = lane & 3;
    const int wm = wid >> 1, wn = wid & 1;   // 4 x 2 warp grid

    const uint32_t qs_u = s2u(Qs);
    const uint32_t ks_u = s2u(Ks);
    const uint32_t ps_u = s2u(Ps);

    const float* qptr  = g_qn + (((size_t)(b * NH + h)) * TT + t0) * DH;
    const float* kbase = g_kn + ((size_t)(b * NH + h)) * SS * DH;
    const float* vbase = g_vh + ((size_t)(b * NH + h)) * SS * DH;
    const float* bptr  = g_biasT + (size_t)h * TT * SS + (size_t)t0 * SS;

    // Stage Q tile once via cp.async (tf32 bits, natural [m][d] layout)
    {
        int row = tid >> 1;
        int dc0 = (tid & 1) * 32;
        const float* qp = qptr + (size_t)row * DH + dc0;
#pragma unroll
        for (int j = 0; j < 8; j++)
            cpa16(qs_u + (uint32_t)((row * W68 + dc0 + j * 4) * 4), qp + j * 4);
        asm volatile("cp.async.commit_group;" ::: "memory");
    }

    float lsum[4] = {0.f, 0.f, 0.f, 0.f};
    float o[2][4][4];
#pragma unroll
    for (int mt = 0; mt < 2; mt++)
#pragma unroll
        for (int nt = 0; nt < 4; nt++)
#pragma unroll
            for (int r = 0; r < 4; r++) o[mt][nt][r] = 0.f;

    for (int s0 = 0; s0 < SS; s0 += 64) {
        __syncthreads();   // prev-iter readers of Ks/Vt/Ps done

        // issue bias + K tile cp.async copies
#pragma unroll
        for (int i = 0; i < 8; i++) {
            cpa16(ps_u + (uint32_t)(((ty * 8 + i) * W68 + tx * 4) * 4),
                  bptr + (size_t)(ty * 8 + i) * SS + s0 + tx * 4);
        }
        {
            int s = tid >> 2;
            int dc = (tid & 3) * 16;
            const float* kp = kbase + (size_t)(s0 + s) * DH + dc;
#pragma unroll
            for (int q = 0; q < 4; q++)
                cpa16(ks_u + (uint32_t)((s * W68 + dc + q * 4) * 4), kp + q * 4);
        }
        asm volatile("cp.async.commit_group;" ::: "memory");

        // V: uint4 LDG + transpose STS (tf32 bits, no conversion)
        {
            int s = tid >> 2;
            int dc = (tid & 3) * 16;
            const uint4* vp = (const uint4*)(vbase + (size_t)(s0 + s) * DH + dc);
            uint32_t* Vb = (uint32_t*)Vt;
#pragma unroll
            for (int q = 0; q < 4; q++) {
                uint4 vv = vp[q];
                int d = dc + q * 4;
                Vb[(d + 0) * W68 + s] = vv.x;
                Vb[(d + 1) * W68 + s] = vv.y;
                Vb[(d + 2) * W68 + s] = vv.z;
                Vb[(d + 3) * W68 + s] = vv.w;
            }
        }
        asm volatile("cp.async.wait_group 0;" ::: "memory");
        __syncthreads();

        // S = Q K^T via mma.sync tf32 (warp tile 32m x 32n, K-dim 64)
        float sf[2][4][4];
#pragma unroll
        for (int mt = 0; mt < 2; mt++)
#pragma unroll
            for (int nt = 0; nt < 4; nt++)
#pragma unroll
                for (int r = 0; r < 4; r++) sf[mt][nt][r] = 0.f;
        {
            const uint32_t* Qb = (const uint32_t*)Qs;
            const uint32_t* Kb = (const uint32_t*)Ks;
#pragma unroll
            for (int k8 = 0; k8 < 8; k8++) {
                const int k = k8 * 8 + tg;
                uint32_t af[2][4], bf[4][2];
#pragma unroll
                for (int mt = 0; mt < 2; mt++) {
                    int r = wm * 32 + mt * 16 + g;
                    af[mt][0] = Qb[r * W68 + k];
                    af[mt][1] = Qb[(r + 8) * W68 + k];
                    af[mt][2] = Qb[r * W68 + k + 4];
                    af[mt][3] = Qb[(r + 8) * W68 + k + 4];
                }
#pragma unroll
                for (int nt = 0; nt < 4; nt++) {
                    int n = wn * 32 + nt * 8 + g;
                    bf[nt][0] = Kb[n * W68 + k];
                    bf[nt][1] = Kb[n * W68 + k + 4];
                }
#pragma unroll
                for (int mt = 0; mt < 2; mt++)
#pragma unroll
                    for (int nt = 0; nt < 4; nt++)
                        mma8(sf[mt][nt], af[mt], bf[nt]);
            }
        }

        // bias (prefetched in Ps) + ex2 in fragment layout; write P into Ps
#pragma unroll
        for (int mt = 0; mt < 2; mt++) {
            int r0 = wm * 32 + mt * 16 + g;
#pragma unroll
            for (int nt = 0; nt < 4; nt++) {
                int c = wn * 32 + nt * 8 + 2 * tg;
                float2 b0 = *(float2*)&Ps[r0 * W68 + c];
                float2 b1 = *(float2*)&Ps[(r0 + 8) * W68 + c];
                float p00 = ex2(sf[mt][nt][0] + b0.x - FIXC);
                float p01 = ex2(sf[mt][nt][1] + b0.y - FIXC);
                float p10 = ex2(sf[mt][nt][2] + b1.x - FIXC);
                float p11 = ex2(sf[mt][nt][3] + b1.y - FIXC);
                lsum[mt * 2 + 0] += p00 + p01;
                lsum[mt * 2 + 1] += p10 + p11;
                *(float2*)&Ps[r0 * W68 + c]       = make_float2(p00, p01);
                *(float2*)&Ps[(r0 + 8) * W68 + c] = make_float2(p10, p11);
            }
        }
        __syncthreads();

        // O += P V (mma.sync tf32; P raw fp32, HW-truncated)
        {
            const uint32_t* Pr = (const uint32_t*)Ps;
            const uint32_t* Vr = (const uint32_t*)Vt;
#pragma unroll
            for (int kk = 0; kk < 8; kk++) {
                const int k = kk * 8 + tg;
                uint32_t af[2][4];
#pragma unroll
                for (int mt = 0; mt < 2; mt++) {
                    int r = wm * 32 + mt * 16 + g;
                    af[mt][0] = Pr[r * W68 + k];
                    af[mt][1] = Pr[(r + 8) * W68 + k];
                    af[mt][2] = Pr[r * W68 + k + 4];
                    af[mt][3] = Pr[(r + 8) * W68 + k + 4];
                }
#pragma unroll
                for (int nt = 0; nt < 4; nt++) {
                    int n = wn * 32 + nt * 8 + g;
                    uint32_t bf[2];
                    bf[0] = Vr[n * W68 + k];
                    bf[1] = Vr[n * W68 + k + 4];
                    mma8(o[0][nt], af[0], bf);
                    mma8(o[1][nt], af[1], bf);
                }
            }
        }
    }

    // reduce lsum over the 4-lane tg group; publish per-row, per-wn sums
#pragma unroll
    for (int i = 0; i < 4; i++) {
        lsum[i] += __shfl_xor_sync(0xffffffffu, lsum[i], 1);
        lsum[i] += __shfl_xor_sync(0xffffffffu, lsum[i], 2);
    }
    if (tg == 0) {
#pragma unroll
        for (int mt = 0; mt < 2; mt++) {
            int r = wm * 32 + mt * 16 + g;
            Ls[wn * 128 + r]     = lsum[mt * 2 + 0];
            Ls[wn * 128 + r + 8] = lsum[mt * 2 + 1];
        }
    }
    __syncthreads();

    // epilogue: normalize O fragments and write to g_vals [B,T,D]
#pragma unroll
    for (int mt = 0; mt < 2; mt++) {
        int r = wm * 32 + mt * 16 + g;
        float inv0 = 1.0f / (Ls[r] + Ls[128 + r]);
        float inv1 = 1.0f / (Ls[r + 8] + Ls[128 + r + 8]);
        float* d0 = g_vals + ((size_t)(b * TT) + t0 + r) * DM + h * DH;
        float* d1 = g_vals + ((size_t)(b * TT) + t0 + r + 8) * DM + h * DH;
#pragma unroll
        for (int nt = 0; nt < 4; nt++) {
            int c = wn * 32 + nt * 8 + 2 * tg;
            *(float2*)(d0 + c) = make_float2(o[mt][nt][0] * inv0, o[mt][nt][1] * inv0);
            *(float2*)(d1 + c) = make_float2(o[mt][nt][2] * inv1, o[mt][nt][3] * inv1);
        }
    }
}

// ---------------------------------------------------------------------------
extern "C" void kernel_launch(void* const* d_in, const int* in_sizes, int n_in,
                              void* d_out, int out_size) {
    const float* q    = (const float*)d_in[0];
    const float* k    = (const float*)d_in[1];
    const float* v    = (const float*)d_in[2];
    const float* bias = (const float*)d_in[3];
    const float* Wqkv = (const float*)d_in[4];
    const float* Wout = (const float*)d_in[5];
    const float* ls   = (const float*)d_in[6];
    float* out = (float*)d_out;

    cudaFuncSetAttribute(attention_kernel,
                         cudaFuncAttributeMaxDynamicSharedMemorySize, ATT_SMEM);
    cudaFuncSetAttribute(fused_pre_kernel,
                         cudaFuncAttributeMaxDynamicSharedMemorySize, PRE_SMEM);
    cudaFuncSetAttribute(gemm_out_kernel,
                         cudaFuncAttributeMaxDynamicSharedMemorySize, PRE_SMEM);

    fused_pre_kernel<<<dim3(32, 8, 4), 256, PRE_SMEM>>>(q, k, v, bias, Wqkv, ls);

    attention_kernel<<<dim3(TT / 128, NH, BB), 256, ATT_SMEM>>>();

    gemm_out_kernel<<<dim3(32, 8), 256, PRE_SMEM>>>(Wout, out);
}

// round 15
// speedup vs baseline: 1.1418x; 1.0364x over previous
#include <cuda_runtime.h>
#include <math.h>
#include <stdint.h>

#define BB 2
#define TT 2048
#define SS 2048
#define DM 1024
#define NH 16
#define DH 64
#define KK 1024

typedef unsigned long long ull;

// Scratch (static device globals — allocation-free rule)
// NOTE: g_qn/g_kn/g_vh hold TF32 BIT PATTERNS (uint32), written by the
// projection epilogue; attention consumes them directly via cp.async/LDG.
__device__ float g_qn[(size_t)BB*NH*TT*DH];
__device__ float g_kn[(size_t)BB*NH*SS*DH];
__device__ float g_vh[(size_t)BB*NH*SS*DH];
__device__ float g_vals[(size_t)BB*TT*DM];     // attention output [B,T,D] (fp32)
__device__ float g_biasT[(size_t)NH*TT*SS];    // bias transposed [H,T,S], x log2e

#define LOG2E 1.4426950408889634f
#define FIXC 24.0f

// ---------------- mma.sync tf32 helpers ----------------
__device__ __forceinline__ uint32_t f2tf(float f) {
    uint32_t r; asm("cvt.rna.tf32.f32 %0, %1;" : "=r"(r) : "f"(f)); return r;
}
__device__ __forceinline__ float ex2(float x) {
    float r; asm("ex2.approx.ftz.f32 %0, %1;" : "=f"(r) : "f"(x)); return r;
}
__device__ __forceinline__ void mma8(float* d, const uint32_t* a, const uint32_t* b) {
    asm("mma.sync.aligned.m16n8k8.row.col.f32.tf32.tf32.f32 "
        "{%0,%1,%2,%3}, {%4,%5,%6,%7}, {%8,%9}, {%0,%1,%2,%3};"
        : "+f"(d[0]), "+f"(d[1]), "+f"(d[2]), "+f"(d[3])
        : "r"(a[0]), "r"(a[1]), "r"(a[2]), "r"(a[3]), "r"(b[0]), "r"(b[1]));
}
__device__ __forceinline__ uint32_t s2u(const void* p) {
    uint32_t a;
    asm("{ .reg .u64 t; cvta.to.shared.u64 t, %1; cvt.u32.u64 %0, t; }"
        : "=r"(a) : "l"(p));
    return a;
}
__device__ __forceinline__ void cpa16(uint32_t dst, const void* src) {
    asm volatile("cp.async.cg.shared.global [%0], [%1], 16;"
                 :: "r"(dst), "l"(src) : "memory");
}

// ---------------------------------------------------------------------------
// Tensor-core GEMM body: C = A[4096,1024] * W[1024,1024]^T.
// CTA 128x128, BK=16, 8 warps (2x4). Single-sync double-buffered mainloop:
// per chunk: [LDG prefetch c+1] -> compute(c) -> store(c+1 -> buf^1) -> sync.
// mode 0: fp32 -> dst_plain   mode 1/2/3: TF32 BITS -> g_vh/g_kn/g_qn
// ---------------------------------------------------------------------------
#define LDK 20
#define ABUF (128 * LDK)
#define PRE_FLOATS (128 * 132)
#define PRE_SMEM (PRE_FLOATS * (int)sizeof(float))

__device__ __forceinline__ void gemm_mma_body(const float* __restrict__ A,
                                              const float* __restrict__ W,
                                              float* __restrict__ dst_plain,
                                              const float* __restrict__ ls,
                                              int mode, float* sm) {
    float* As = sm;
    float* Bs = sm + 2 * ABUF;
    float* Cs = sm;
    const int m0 = blockIdx.x * 128;
    const int n0 = blockIdx.y * 128;
    const int tid = threadIdx.x;
    const int wid = tid >> 5, lane = tid & 31;
    const int wm = wid >> 2, wn = wid & 3;
    const int g = lane >> 2, tg = lane & 3;

    const int srow = tid >> 1;
    const int skc = (tid & 1) * 8;
    const float* aP = A + (size_t)(m0 + srow) * KK + skc;
    const float* wP = W + (size_t)(n0 + srow) * KK + skc;

    float d[4][4][4];
#pragma unroll
    for (int mt = 0; mt < 4; mt++)
#pragma unroll
        for (int nt = 0; nt < 4; nt++)
#pragma unroll
            for (int r = 0; r < 4; r++) d[mt][nt][r] = 0.f;

    // prologue: load + store chunk 0, one sync
    {
        float4 a0 = *(const float4*)(aP), a1 = *(const float4*)(aP + 4);
        float4 w0 = *(const float4*)(wP), w1 = *(const float4*)(wP + 4);
        uint32_t* ad = (uint32_t*)(As + srow * LDK + skc);
        uint32_t* bd = (uint32_t*)(Bs + srow * LDK + skc);
        ad[0] = f2tf(a0.x); ad[1] = f2tf(a0.y); ad[2] = f2tf(a0.z); ad[3] = f2tf(a0.w);
        ad[4] = f2tf(a1.x); ad[5] = f2tf(a1.y); ad[6] = f2tf(a1.z); ad[7] = f2tf(a1.w);
        bd[0] = f2tf(w0.x); bd[1] = f2tf(w0.y); bd[2] = f2tf(w0.z); bd[3] = f2tf(w0.w);
        bd[4] = f2tf(w1.x); bd[5] = f2tf(w1.y); bd[6] = f2tf(w1.z); bd[7] = f2tf(w1.w);
    }
    __syncthreads();

    const int NC = KK / 16;
    for (int c = 0; c < NC; c++) {
        const int buf = c & 1;
        float4 ra0, ra1, rw0, rw1;
        if (c + 1 < NC) {
            int ko = (c + 1) * 16;
            ra0 = *(const float4*)(aP + ko);  ra1 = *(const float4*)(aP + ko + 4);
            rw0 = *(const float4*)(wP + ko);  rw1 = *(const float4*)(wP + ko + 4);
        }
        // compute chunk c
        const uint32_t* Ab = (const uint32_t*)(As + buf * ABUF);
        const uint32_t* Bb = (const uint32_t*)(Bs + buf * ABUF);
#pragma unroll
        for (int ks = 0; ks < 2; ks++) {
            const int k = ks * 8 + tg;
            uint32_t af[4][4], bf[4][2];
#pragma unroll
            for (int mt = 0; mt < 4; mt++) {
                int r = wm * 64 + mt * 16 + g;
                af[mt][0] = Ab[r * LDK + k];
                af[mt][1] = Ab[(r + 8) * LDK + k];
                af[mt][2] = Ab[r * LDK + k + 4];
                af[mt][3] = Ab[(r + 8) * LDK + k + 4];
            }
#pragma unroll
            for (int nt = 0; nt < 4; nt++) {
                int n = wn * 32 + nt * 8 + g;
                bf[nt][0] = Bb[n * LDK + k];
                bf[nt][1] = Bb[n * LDK + k + 4];
            }
#pragma unroll
            for (int mt = 0; mt < 4; mt++)
#pragma unroll
                for (int nt = 0; nt < 4; nt++)
                    mma8(d[mt][nt], af[mt], bf[nt]);
        }
        // store chunk c+1 into the other buffer
        if (c + 1 < NC) {
            const int nb = (c + 1) & 1;
            uint32_t* ad = (uint32_t*)(As + nb * ABUF + srow * LDK + skc);
            uint32_t* bd = (uint32_t*)(Bs + nb * ABUF + srow * LDK + skc);
            ad[0] = f2tf(ra0.x); ad[1] = f2tf(ra0.y); ad[2] = f2tf(ra0.z); ad[3] = f2tf(ra0.w);
            ad[4] = f2tf(ra1.x); ad[5] = f2tf(ra1.y); ad[6] = f2tf(ra1.z); ad[7] = f2tf(ra1.w);
            bd[0] = f2tf(rw0.x); bd[1] = f2tf(rw0.y); bd[2] = f2tf(rw0.z); bd[3] = f2tf(rw0.w);
            bd[4] = f2tf(rw1.x); bd[5] = f2tf(rw1.y); bd[6] = f2tf(rw1.z); bd[7] = f2tf(rw1.w);
        }
        __syncthreads();
    }

    const int g2 = g, tg2 = tg;
#pragma unroll
    for (int mt = 0; mt < 4; mt++) {
        int r = wm * 64 + mt * 16 + g2;
#pragma unroll
        for (int nt = 0; nt < 4; nt++) {
            int cc = wn * 32 + nt * 8 + 2 * tg2;
            *(float2*)&Cs[r * 132 + cc]       = make_float2(d[mt][nt][0], d[mt][nt][1]);
            *(float2*)&Cs[(r + 8) * 132 + cc] = make_float2(d[mt][nt][2], d[mt][nt][3]);
        }
    }
    __syncthreads();

    {
        const int row = tid >> 1;
        const int half = tid & 1;
        float f[64];
        const float* src = &Cs[row * 132 + half * 64];
#pragma unroll
        for (int j = 0; j < 16; j++) {
            float4 v = *(const float4*)(src + j * 4);
            f[4 * j] = v.x; f[4 * j + 1] = v.y; f[4 * j + 2] = v.z; f[4 * j + 3] = v.w;
        }
        if (mode >= 2) {
            float ssq = 0.f;
#pragma unroll
            for (int j = 0; j < 64; j++) ssq += f[j] * f[j];
            float hs = 1.0f;
            if (mode == 3)   // fold log2e into Q's logit scale (log2-domain softmax)
                hs = expf(fminf(ls[blockIdx.y * 2 + half], 4.6051701859880914f)) * LOG2E;
            float inv = hs / fmaxf(sqrtf(ssq), 1e-12f);
#pragma unroll
            for (int j = 0; j < 64; j++) f[j] *= inv;
        }
        const int m = m0 + row;
        if (mode == 0) {
            float* dst = dst_plain + (size_t)m * DM + n0 + half * 64;
#pragma unroll
            for (int j = 0; j < 16; j++)
                *(float4*)(dst + j * 4) =
                    make_float4(f[4 * j], f[4 * j + 1], f[4 * j + 2], f[4 * j + 3]);
        } else {
            // store TF32 BIT PATTERNS (consumed directly by attention mma)
            int b = m >> 11, t = m & 2047;
            int h = (n0 >> 6) + half;
            float* base = (mode == 1) ? g_vh : (mode == 2) ? g_kn : g_qn;
            uint32_t* dst = (uint32_t*)(base + (((size_t)(b * NH + h)) * TT + t) * DH);
#pragma unroll
            for (int j = 0; j < 16; j++) {
                uint4 u;
                u.x = f2tf(f[4 * j]);
                u.y = f2tf(f[4 * j + 1]);
                u.z = f2tf(f[4 * j + 2]);
                u.w = f2tf(f[4 * j + 3]);
                *(uint4*)(dst + j * 4) = u;
            }
        }
    }
}

// ---------------------------------------------------------------------------
// Bias transpose: [T,S,H] -> [H,T,S], scaled by log2e.
// ---------------------------------------------------------------------------
__device__ __forceinline__ void transpose_body(const float* __restrict__ in, float* sm) {
    const int c = blockIdx.y * 32 + blockIdx.x;
    const int tid = threadIdx.x;
    for (int tb = 0; tb < 2; tb++) {
        const int t0 = (c * 2 + tb) * 4;
        for (int s0 = 0; s0 < SS; s0 += 64) {
#pragma unroll
            for (int tt = 0; tt < 4; tt++) {
                const float* src = in + ((size_t)(t0 + tt) * SS + s0) * NH;
#pragma unroll
                for (int p = 0; p < 4; p++) {
                    int idx = p * 256 + tid;
                    int h = idx & 15, ss = idx >> 4;
                    sm[h * 261 + tt * 64 + ss] = src[idx] * LOG2E;
                }
            }
            __syncthreads();
#pragma unroll
            for (int p = 0; p < 16; p++) {
                int idx = p * 256 + tid;
                int ss = idx & 63;
                int combo = idx >> 6;
                int tt = combo & 3, h = combo >> 2;
                g_biasT[(size_t)h * TT * SS + (size_t)(t0 + tt) * SS + s0 + ss] =
                    sm[h * 261 + tt * 64 + ss];
            }
            __syncthreads();
        }
    }
}

__global__ __launch_bounds__(256, 2) void fused_pre_kernel(const float* __restrict__ q,
                                                           const float* __restrict__ k,
                                                           const float* __restrict__ v,
                                                           const float* __restrict__ bias,
                                                           const float* __restrict__ Wqkv,
                                                           const float* __restrict__ ls) {
    extern __shared__ float sm[];
    const int z = blockIdx.z;
    if (z == 0)      gemm_mma_body(q, Wqkv, nullptr, ls, 3, sm);
    else if (z == 1) gemm_mma_body(k, Wqkv, nullptr, nullptr, 2, sm);
    else if (z == 2) gemm_mma_body(v, Wqkv, nullptr, nullptr, 1, sm);
    else             transpose_body(bias, sm);
}

__global__ __launch_bounds__(256, 2) void gemm_out_kernel(const float* __restrict__ Wout,
                                                          float* __restrict__ out) {
    extern __shared__ float sm[];
    gemm_mma_body((const float*)g_vals, Wout, out, nullptr, 0, sm);
}

// ---------------------------------------------------------------------------
// Flash attention v5 (R14-verbatim): BM=128(t), BN=64(s), 256 thr, all-tensor.
// Q/K staged via cp.async (tf32 bits in gmem). V: uint4 LDG + transpose STS.
// Smem: Qs[128][68] | Ks[64][68] | Vt[64][68] | Ps[128][68] | Ls[2][128].
// ---------------------------------------------------------------------------
#define W68 68
#define ATT_FLOATS (128*W68 + 64*W68 + 64*W68 + 128*W68 + 256)
#define ATT_SMEM (ATT_FLOATS * (int)sizeof(float))

__global__ __launch_bounds__(256, 2) void attention_kernel() {
    extern __shared__ float sm[];
    float* Qs = sm;                         // [128][68] tf32 bits
    float* Ks = sm + 128 * W68;             // [64][68] tf32 bits
    float* Vt = Ks + 64 * W68;              // [64][68] tf32 bits (dh-major)
    float* Ps = Vt + 64 * W68;              // [128][68]  (bias, then P)
    float* Ls = Ps + 128 * W68;             // [2][128]

    const int t0 = blockIdx.x * 128;
    const int h = blockIdx.y;
    const int b = blockIdx.z;
    const int tid = threadIdx.x;
    const int tx = tid & 15, ty = tid >> 4;
    const int wid = tid >> 5, lane = tid & 31;
    const int g = lane >> 2, tg = lane & 3;
    const int wm = wid >> 1, wn = wid & 1;   // 4 x 2 warp grid

    const uint32_t qs_u = s2u(Qs);
    const uint32_t ks_u = s2u(Ks);
    const uint32_t ps_u = s2u(Ps);

    const float* qptr  = g_qn + (((size_t)(b * NH + h)) * TT + t0) * DH;
    const float* kbase = g_kn + ((size_t)(b * NH + h)) * SS * DH;
    const float* vbase = g_vh + ((size_t)(b * NH + h)) * SS * DH;
    const float* bptr  = g_biasT + (size_t)h * TT * SS + (size_t)t0 * SS;

    // Stage Q tile once via cp.async (tf32 bits, natural [m][d] layout)
    {
        int row = tid >> 1;
        int dc0 = (tid & 1) * 32;
        const float* qp = qptr + (size_t)row * DH + dc0;
#pragma unroll
        for (int j = 0; j < 8; j++)
            cpa16(qs_u + (uint32_t)((row * W68 + dc0 + j * 4) * 4), qp + j * 4);
        asm volatile("cp.async.commit_group;" ::: "memory");
    }

    float lsum[4] = {0.f, 0.f, 0.f, 0.f};
    float o[2][4][4];
#pragma unroll
    for (int mt = 0; mt < 2; mt++)
#pragma unroll
        for (int nt = 0; nt < 4; nt++)
#pragma unroll
            for (int r = 0; r < 4; r++) o[mt][nt][r] = 0.f;

    for (int s0 = 0; s0 < SS; s0 += 64) {
        __syncthreads();   // prev-iter readers of Ks/Vt/Ps done

        // issue bias + K tile cp.async copies
#pragma unroll
        for (int i = 0; i < 8; i++) {
            cpa16(ps_u + (uint32_t)(((ty * 8 + i) * W68 + tx * 4) * 4),
                  bptr + (size_t)(ty * 8 + i) * SS + s0 + tx * 4);
        }
        {
            int s = tid >> 2;
            int dc = (tid & 3) * 16;
            const float* kp = kbase + (size_t)(s0 + s) * DH + dc;
#pragma unroll
            for (int q = 0; q < 4; q++)
                cpa16(ks_u + (uint32_t)((s * W68 + dc + q * 4) * 4), kp + q * 4);
        }
        asm volatile("cp.async.commit_group;" ::: "memory");

        // V: uint4 LDG + transpose STS (tf32 bits, no conversion)
        {
            int s = tid >> 2;
            int dc = (tid & 3) * 16;
            const uint4* vp = (const uint4*)(vbase + (size_t)(s0 + s) * DH + dc);
            uint32_t* Vb = (uint32_t*)Vt;
#pragma unroll
            for (int q = 0; q < 4; q++) {
                uint4 vv = vp[q];
                int d = dc + q * 4;
                Vb[(d + 0) * W68 + s] = vv.x;
                Vb[(d + 1) * W68 + s] = vv.y;
                Vb[(d + 2) * W68 + s] = vv.z;
                Vb[(d + 3) * W68 + s] = vv.w;
            }
        }
        asm volatile("cp.async.wait_group 0;" ::: "memory");
        __syncthreads();

        // S = Q K^T via mma.sync tf32 (warp tile 32m x 32n, K-dim 64)
        float sf[2][4][4];
#pragma unroll
        for (int mt = 0; mt < 2; mt++)
#pragma unroll
            for (int nt = 0; nt < 4; nt++)
#pragma unroll
                for (int r = 0; r < 4; r++) sf[mt][nt][r] = 0.f;
        {
            const uint32_t* Qb = (const uint32_t*)Qs;
            const uint32_t* Kb = (const uint32_t*)Ks;
#pragma unroll
            for (int k8 = 0; k8 < 8; k8++) {
                const int k = k8 * 8 + tg;
                uint32_t af[2][4], bf[4][2];
#pragma unroll
                for (int mt = 0; mt < 2; mt++) {
                    int r = wm * 32 + mt * 16 + g;
                    af[mt][0] = Qb[r * W68 + k];
                    af[mt][1] = Qb[(r + 8) * W68 + k];
                    af[mt][2] = Qb[r * W68 + k + 4];
                    af[mt][3] = Qb[(r + 8) * W68 + k + 4];
                }
#pragma unroll
                for (int nt = 0; nt < 4; nt++) {
                    int n = wn * 32 + nt * 8 + g;
                    bf[nt][0] = Kb[n * W68 + k];
                    bf[nt][1] = Kb[n * W68 + k + 4];
                }
#pragma unroll
                for (int mt = 0; mt < 2; mt++)
#pragma unroll
                    for (int nt = 0; nt < 4; nt++)
                        mma8(sf[mt][nt], af[mt], bf[nt]);
            }
        }

        // bias (prefetched in Ps) + ex2 in fragment layout; write P into Ps
#pragma unroll
        for (int mt = 0; mt < 2; mt++) {
            int r0 = wm * 32 + mt * 16 + g;
#pragma unroll
            for (int nt = 0; nt < 4; nt++) {
                int c = wn * 32 + nt * 8 + 2 * tg;
                float2 b0 = *(float2*)&Ps[r0 * W68 + c];
                float2 b1 = *(float2*)&Ps[(r0 + 8) * W68 + c];
                float p00 = ex2(sf[mt][nt][0] + b0.x - FIXC);
                float p01 = ex2(sf[mt][nt][1] + b0.y - FIXC);
                float p10 = ex2(sf[mt][nt][2] + b1.x - FIXC);
                float p11 = ex2(sf[mt][nt][3] + b1.y - FIXC);
                lsum[mt * 2 + 0] += p00 + p01;
                lsum[mt * 2 + 1] += p10 + p11;
                *(float2*)&Ps[r0 * W68 + c]       = make_float2(p00, p01);
                *(float2*)&Ps[(r0 + 8) * W68 + c] = make_float2(p10, p11);
            }
        }
        __syncthreads();

        // O += P V (mma.sync tf32; P raw fp32, HW-truncated)
        {
            const uint32_t* Pr = (const uint32_t*)Ps;
            const uint32_t* Vr = (const uint32_t*)Vt;
#pragma unroll
            for (int kk = 0; kk < 8; kk++) {
                const int k = kk * 8 + tg;
                uint32_t af[2][4];
#pragma unroll
                for (int mt = 0; mt < 2; mt++) {
                    int r = wm * 32 + mt * 16 + g;
                    af[mt][0] = Pr[r * W68 + k];
                    af[mt][1] = Pr[(r + 8) * W68 + k];
                    af[mt][2] = Pr[r * W68 + k + 4];
                    af[mt][3] = Pr[(r + 8) * W68 + k + 4];
                }
#pragma unroll
                for (int nt = 0; nt < 4; nt++) {
                    int n = wn * 32 + nt * 8 + g;
                    uint32_t bf[2];
                    bf[0] = Vr[n * W68 + k];
                    bf[1] = Vr[n * W68 + k + 4];
                    mma8(o[0][nt], af[0], bf);
                    mma8(o[1][nt], af[1], bf);
                }
            }
        }
    }

    // reduce lsum over the 4-lane tg group; publish per-row, per-wn sums
#pragma unroll
    for (int i = 0; i < 4; i++) {
        lsum[i] += __shfl_xor_sync(0xffffffffu, lsum[i], 1);
        lsum[i] += __shfl_xor_sync(0xffffffffu, lsum[i], 2);
    }
    if (tg == 0) {
#pragma unroll
        for (int mt = 0; mt < 2; mt++) {
            int r = wm * 32 + mt * 16 + g;
            Ls[wn * 128 + r]     = lsum[mt * 2 + 0];
            Ls[wn * 128 + r + 8] = lsum[mt * 2 + 1];
        }
    }
    __syncthreads();

    // epilogue: normalize O fragments and write to g_vals [B,T,D]
#pragma unroll
    for (int mt = 0; mt < 2; mt++) {
        int r = wm * 32 + mt * 16 + g;
        float inv0 = 1.0f / (Ls[r] + Ls[128 + r]);
        float inv1 = 1.0f / (Ls[r + 8] + Ls[128 + r + 8]);
        float* d0 = g_vals + ((size_t)(b * TT) + t0 + r) * DM + h * DH;
        float* d1 = g_vals + ((size_t)(b * TT) + t0 + r + 8) * DM + h * DH;
#pragma unroll
        for (int nt = 0; nt < 4; nt++) {
            int c = wn * 32 + nt * 8 + 2 * tg;
            *(float2*)(d0 + c) = make_float2(o[mt][nt][0] * inv0, o[mt][nt][1] * inv0);
            *(float2*)(d1 + c) = make_float2(o[mt][nt][2] * inv1, o[mt][nt][3] * inv1);
        }
    }
}

// ---------------------------------------------------------------------------
extern "C" void kernel_launch(void* const* d_in, const int* in_sizes, int n_in,
                              void* d_out, int out_size) {
    const float* q    = (const float*)d_in[0];
    const float* k    = (const float*)d_in[1];
    const float* v    = (const float*)d_in[2];
    const float* bias = (const float*)d_in[3];
    const float* Wqkv = (const float*)d_in[4];
    const float* Wout = (const float*)d_in[5];
    const float* ls   = (const float*)d_in[6];
    float* out = (float*)d_out;

    cudaFuncSetAttribute(attention_kernel,
                         cudaFuncAttributeMaxDynamicSharedMemorySize, ATT_SMEM);
    cudaFuncSetAttribute(fused_pre_kernel,
                         cudaFuncAttributeMaxDynamicSharedMemorySize, PRE_SMEM);
    cudaFuncSetAttribute(gemm_out_kernel,
                         cudaFuncAttributeMaxDynamicSharedMemorySize, PRE_SMEM);

    fused_pre_kernel<<<dim3(32, 8, 4), 256, PRE_SMEM>>>(q, k, v, bias, Wqkv, ls);

    attention_kernel<<<dim3(TT / 128, NH, BB), 256, ATT_SMEM>>>();

    gemm_out_kernel<<<dim3(32, 8), 256, PRE_SMEM>>>(Wout, out);
}

// round 16
// speedup vs baseline: 1.1704x; 1.0250x over previous
#include <cuda_runtime.h>
#include <math.h>
#include <stdint.h>

#define BB 2
#define TT 2048
#define SS 2048
#define DM 1024
#define NH 16
#define DH 64
#define KK 1024

// Scratch (static device globals — allocation-free rule)
// g_qn/g_kn/g_vh/g_vals hold TF32 BIT PATTERNS; g_c* are pre-converted inputs.
__device__ float g_qn[(size_t)BB*NH*TT*DH];
__device__ float g_kn[(size_t)BB*NH*SS*DH];
__device__ float g_vh[(size_t)BB*NH*SS*DH];
__device__ float g_vals[(size_t)BB*TT*DM];     // attention out, TF32 bits
__device__ float g_biasT[(size_t)NH*TT*SS];    // bias [H,T,S], x log2e (fp32)
__device__ uint32_t g_cq[(size_t)4096*1024];   // tf32 bits of q
__device__ uint32_t g_ck[(size_t)4096*1024];   // tf32 bits of k
__device__ uint32_t g_cv[(size_t)4096*1024];   // tf32 bits of v
__device__ uint32_t g_cw[(size_t)1024*1024];   // tf32 bits of Wqkv
__device__ uint32_t g_cwo[(size_t)1024*1024];  // tf32 bits of Wout

#define LOG2E 1.4426950408889634f
#define FIXC 24.0f

// ---------------- mma.sync tf32 helpers ----------------
__device__ __forceinline__ uint32_t f2tf(float f) {
    uint32_t r; asm("cvt.rna.tf32.f32 %0, %1;" : "=r"(r) : "f"(f)); return r;
}
__device__ __forceinline__ float ex2(float x) {
    float r; asm("ex2.approx.ftz.f32 %0, %1;" : "=f"(r) : "f"(x)); return r;
}
__device__ __forceinline__ void mma8(float* d, const uint32_t* a, const uint32_t* b) {
    asm("mma.sync.aligned.m16n8k8.row.col.f32.tf32.tf32.f32 "
        "{%0,%1,%2,%3}, {%4,%5,%6,%7}, {%8,%9}, {%0,%1,%2,%3};"
        : "+f"(d[0]), "+f"(d[1]), "+f"(d[2]), "+f"(d[3])
        : "r"(a[0]), "r"(a[1]), "r"(a[2]), "r"(a[3]), "r"(b[0]), "r"(b[1]));
}
__device__ __forceinline__ uint32_t s2u(const void* p) {
    uint32_t a;
    asm("{ .reg .u64 t; cvta.to.shared.u64 t, %1; cvt.u32.u64 %0, t; }"
        : "=r"(a) : "l"(p));
    return a;
}
__device__ __forceinline__ void cpa16(uint32_t dst, const void* src) {
    asm volatile("cp.async.cg.shared.global [%0], [%1], 16;"
                 :: "r"(dst), "l"(src) : "memory");
}

// ---------------------------------------------------------------------------
// Pre-convert inputs to tf32 bit patterns (q,k,v,Wqkv,Wout). Grid (4096, 5).
// ---------------------------------------------------------------------------
__global__ __launch_bounds__(256) void convert_kernel(const float* __restrict__ q,
                                                      const float* __restrict__ k,
                                                      const float* __restrict__ v,
                                                      const float* __restrict__ wqkv,
                                                      const float* __restrict__ wout) {
    const int z = blockIdx.y;
    const float* src; uint32_t* dst; size_t n;
    if (z == 0)      { src = q;    dst = g_cq;  n = (size_t)4096 * 1024; }
    else if (z == 1) { src = k;    dst = g_ck;  n = (size_t)4096 * 1024; }
    else if (z == 2) { src = v;    dst = g_cv;  n = (size_t)4096 * 1024; }
    else if (z == 3) { src = wqkv; dst = g_cw;  n = (size_t)1024 * 1024; }
    else             { src = wout; dst = g_cwo; n = (size_t)1024 * 1024; }
    size_t i = ((size_t)blockIdx.x * 256 + threadIdx.x) * 4;
    if (i < n) {
        float4 vv = *(const float4*)(src + i);
        uint4 u;
        u.x = f2tf(vv.x); u.y = f2tf(vv.y); u.z = f2tf(vv.z); u.w = f2tf(vv.w);
        *(uint4*)(dst + i) = u;
    }
}

// ---------------------------------------------------------------------------
// Tensor-core GEMM body, all-cp.async 3-stage pipeline, operands = tf32 bits.
// CTA 128x128, BK=16, 8 warps (2x4). One sync per chunk.
// mode 0: fp32 -> dst_plain   mode 1/2/3: TF32 BITS -> g_vh/g_kn/g_qn
// ---------------------------------------------------------------------------
#define LDK 20
#define NSTG 3
#define STGF (128 * LDK)                 // floats per operand-stage
#define PRE_FLOATS (128 * 132)           // Cs overlay (16896 > 3*2*2560)
#define PRE_SMEM (PRE_FLOATS * (int)sizeof(float))

__device__ __forceinline__ void gemm_bits_body(const uint32_t* __restrict__ Abits,
                                               const uint32_t* __restrict__ Wbits,
                                               float* __restrict__ dst_plain,
                                               const float* __restrict__ ls,
                                               int mode, float* sm) {
    float* Cs = sm;
    const int m0 = blockIdx.x * 128;
    const int n0 = blockIdx.y * 128;
    const int tid = threadIdx.x;
    const int wid = tid >> 5, lane = tid & 31;
    const int wm = wid >> 2, wn = wid & 3;
    const int g = lane >> 2, tg = lane & 3;

    const uint32_t sm_u = s2u(sm);
    const int srow = tid >> 1;
    const int skc = (tid & 1) * 8;
    const uint32_t* aP = Abits + (size_t)(m0 + srow) * KK + skc;
    const uint32_t* wP = Wbits + (size_t)(n0 + srow) * KK + skc;
    const uint32_t a_dst = sm_u + (uint32_t)((srow * LDK + skc) * 4);
    const uint32_t b_dst = sm_u + (uint32_t)(NSTG * STGF * 4) +
                           (uint32_t)((srow * LDK + skc) * 4);

    float d[4][4][4];
#pragma unroll
    for (int mt = 0; mt < 4; mt++)
#pragma unroll
        for (int nt = 0; nt < 4; nt++)
#pragma unroll
            for (int r = 0; r < 4; r++) d[mt][nt][r] = 0.f;

#define G_ISSUE(c) do {                                            \
        const int st_ = (c) % NSTG;                                \
        cpa16(a_dst + (uint32_t)(st_ * STGF * 4), aP + (c) * 16);       \
        cpa16(a_dst + (uint32_t)(st_ * STGF * 4) + 16, aP + (c) * 16 + 4); \
        cpa16(b_dst + (uint32_t)(st_ * STGF * 4), wP + (c) * 16);       \
        cpa16(b_dst + (uint32_t)(st_ * STGF * 4) + 16, wP + (c) * 16 + 4); \
        asm volatile("cp.async.commit_group;" ::: "memory");       \
    } while (0)

    const int NC = KK / 16;   // 64
    G_ISSUE(0);
    G_ISSUE(1);

    for (int c = 0; c < NC; c++) {
        if (c + 1 < NC)
            asm volatile("cp.async.wait_group 1;" ::: "memory");
        else
            asm volatile("cp.async.wait_group 0;" ::: "memory");
        __syncthreads();
        if (c + 2 < NC) G_ISSUE(c + 2);

        const uint32_t* Ab = (const uint32_t*)sm + (c % NSTG) * STGF;
        const uint32_t* Bb = (const uint32_t*)sm + NSTG * STGF + (c % NSTG) * STGF;
#pragma unroll
        for (int ks = 0; ks < 2; ks++) {
            const int k = ks * 8 + tg;
            uint32_t af[4][4], bf[4][2];
#pragma unroll
            for (int mt = 0; mt < 4; mt++) {
                int r = wm * 64 + mt * 16 + g;
                af[mt][0] = Ab[r * LDK + k];
                af[mt][1] = Ab[(r + 8) * LDK + k];
                af[mt][2] = Ab[r * LDK + k + 4];
                af[mt][3] = Ab[(r + 8) * LDK + k + 4];
            }
#pragma unroll
            for (int nt = 0; nt < 4; nt++) {
                int n = wn * 32 + nt * 8 + g;
                bf[nt][0] = Bb[n * LDK + k];
                bf[nt][1] = Bb[n * LDK + k + 4];
            }
#pragma unroll
            for (int mt = 0; mt < 4; mt++)
#pragma unroll
                for (int nt = 0; nt < 4; nt++)
                    mma8(d[mt][nt], af[mt], bf[nt]);
        }
    }
    __syncthreads();   // all computes done before Cs overlay writes

#pragma unroll
    for (int mt = 0; mt < 4; mt++) {
        int r = wm * 64 + mt * 16 + g;
#pragma unroll
        for (int nt = 0; nt < 4; nt++) {
            int cc = wn * 32 + nt * 8 + 2 * tg;
            *(float2*)&Cs[r * 132 + cc]       = make_float2(d[mt][nt][0], d[mt][nt][1]);
            *(float2*)&Cs[(r + 8) * 132 + cc] = make_float2(d[mt][nt][2], d[mt][nt][3]);
        }
    }
    __syncthreads();

    {
        const int row = tid >> 1;
        const int half = tid & 1;
        float f[64];
        const float* src = &Cs[row * 132 + half * 64];
#pragma unroll
        for (int j = 0; j < 16; j++) {
            float4 v = *(const float4*)(src + j * 4);
            f[4 * j] = v.x; f[4 * j + 1] = v.y; f[4 * j + 2] = v.z; f[4 * j + 3] = v.w;
        }
        if (mode >= 2) {
            float ssq = 0.f;
#pragma unroll
            for (int j = 0; j < 64; j++) ssq += f[j] * f[j];
            float hs = 1.0f;
            if (mode == 3)   // fold log2e into Q's logit scale (log2-domain softmax)
                hs = expf(fminf(ls[blockIdx.y * 2 + half], 4.6051701859880914f)) * LOG2E;
            float inv = hs / fmaxf(sqrtf(ssq), 1e-12f);
#pragma unroll
            for (int j = 0; j < 64; j++) f[j] *= inv;
        }
        const int m = m0 + row;
        if (mode == 0) {
            float* dst = dst_plain + (size_t)m * DM + n0 + half * 64;
#pragma unroll
            for (int j = 0; j < 16; j++)
                *(float4*)(dst + j * 4) =
                    make_float4(f[4 * j], f[4 * j + 1], f[4 * j + 2], f[4 * j + 3]);
        } else {
            int b = m >> 11, t = m & 2047;
            int h = (n0 >> 6) + half;
            float* base = (mode == 1) ? g_vh : (mode == 2) ? g_kn : g_qn;
            uint32_t* dst = (uint32_t*)(base + (((size_t)(b * NH + h)) * TT + t) * DH);
#pragma unroll
            for (int j = 0; j < 16; j++) {
                uint4 u;
                u.x = f2tf(f[4 * j]);
                u.y = f2tf(f[4 * j + 1]);
                u.z = f2tf(f[4 * j + 2]);
                u.w = f2tf(f[4 * j + 3]);
                *(uint4*)(dst + j * 4) = u;
            }
        }
    }
}

// ---------------------------------------------------------------------------
// Bias transpose: [T,S,H] -> [H,T,S], scaled by log2e.
// ---------------------------------------------------------------------------
__device__ __forceinline__ void transpose_body(const float* __restrict__ in, float* sm) {
    const int c = blockIdx.y * 32 + blockIdx.x;
    const int tid = threadIdx.x;
    for (int tb = 0; tb < 2; tb++) {
        const int t0 = (c * 2 + tb) * 4;
        for (int s0 = 0; s0 < SS; s0 += 64) {
#pragma unroll
            for (int tt = 0; tt < 4; tt++) {
                const float* src = in + ((size_t)(t0 + tt) * SS + s0) * NH;
#pragma unroll
                for (int p = 0; p < 4; p++) {
                    int idx = p * 256 + tid;
                    int h = idx & 15, ss = idx >> 4;
                    sm[h * 261 + tt * 64 + ss] = src[idx] * LOG2E;
                }
            }
            __syncthreads();
#pragma unroll
            for (int p = 0; p < 16; p++) {
                int idx = p * 256 + tid;
                int ss = idx & 63;
                int combo = idx >> 6;
                int tt = combo & 3, h = combo >> 2;
                g_biasT[(size_t)h * TT * SS + (size_t)(t0 + tt) * SS + s0 + ss] =
                    sm[h * 261 + tt * 64 + ss];
            }
            __syncthreads();
        }
    }
}

__global__ __launch_bounds__(256, 2) void fused_pre_kernel(const float* __restrict__ bias,
                                                           const float* __restrict__ ls) {
    extern __shared__ float sm[];
    const int z = blockIdx.z;
    if (z == 0)      gemm_bits_body(g_cq, g_cw, nullptr, ls, 3, sm);
    else if (z == 1) gemm_bits_body(g_ck, g_cw, nullptr, nullptr, 2, sm);
    else if (z == 2) gemm_bits_body(g_cv, g_cw, nullptr, nullptr, 1, sm);
    else             transpose_body(bias, sm);
}

__global__ __launch_bounds__(256, 2) void gemm_out_kernel(float* __restrict__ out) {
    extern __shared__ float sm[];
    gemm_bits_body((const uint32_t*)g_vals, g_cwo, out, nullptr, 0, sm);
}

// ---------------------------------------------------------------------------
// Flash attention (R15 + tf32-bits epilogue): BM=128(t), BN=64(s), 256 thr.
// Q/K staged via cp.async (tf32 bits). V: uint4 LDG + transpose STS.
// Smem: Qs[128][68] | Ks[64][68] | Vt[64][68] | Ps[128][68] | Ls[2][128].
// ---------------------------------------------------------------------------
#define W68 68
#define ATT_FLOATS (128*W68 + 64*W68 + 64*W68 + 128*W68 + 256)
#define ATT_SMEM (ATT_FLOATS * (int)sizeof(float))

__global__ __launch_bounds__(256, 2) void attention_kernel() {
    extern __shared__ float sm[];
    float* Qs = sm;                         // [128][68] tf32 bits
    float* Ks = sm + 128 * W68;             // [64][68] tf32 bits
    float* Vt = Ks + 64 * W68;              // [64][68] tf32 bits (dh-major)
    float* Ps = Vt + 64 * W68;              // [128][68]  (bias, then P)
    float* Ls = Ps + 128 * W68;             // [2][128]

    const int t0 = blockIdx.x * 128;
    const int h = blockIdx.y;
    const int b = blockIdx.z;
    const int tid = threadIdx.x;
    const int tx = tid & 15, ty = tid >> 4;
    const int wid = tid >> 5, lane = tid & 31;
    const int g = lane >> 2, tg = lane & 3;
    const int wm = wid >> 1, wn = wid & 1;   // 4 x 2 warp grid

    const uint32_t qs_u = s2u(Qs);
    const uint32_t ks_u = s2u(Ks);
    const uint32_t ps_u = s2u(Ps);

    const float* qptr  = g_qn + (((size_t)(b * NH + h)) * TT + t0) * DH;
    const float* kbase = g_kn + ((size_t)(b * NH + h)) * SS * DH;
    const float* vbase = g_vh + ((size_t)(b * NH + h)) * SS * DH;
    const float* bptr  = g_biasT + (size_t)h * TT * SS + (size_t)t0 * SS;

    // Stage Q tile once via cp.async (tf32 bits, natural [m][d] layout)
    {
        int row = tid >> 1;
        int dc0 = (tid & 1) * 32;
        const float* qp = qptr + (size_t)row * DH + dc0;
#pragma unroll
        for (int j = 0; j < 8; j++)
            cpa16(qs_u + (uint32_t)((row * W68 + dc0 + j * 4) * 4), qp + j * 4);
        asm volatile("cp.async.commit_group;" ::: "memory");
    }

    float lsum[4] = {0.f, 0.f, 0.f, 0.f};
    float o[2][4][4];
#pragma unroll
    for (int mt = 0; mt < 2; mt++)
#pragma unroll
        for (int nt = 0; nt < 4; nt++)
#pragma unroll
            for (int r = 0; r < 4; r++) o[mt][nt][r] = 0.f;

    for (int s0 = 0; s0 < SS; s0 += 64) {
        __syncthreads();   // prev-iter readers of Ks/Vt/Ps done

        // issue bias + K tile cp.async copies
#pragma unroll
        for (int i = 0; i < 8; i++) {
            cpa16(ps_u + (uint32_t)(((ty * 8 + i) * W68 + tx * 4) * 4),
                  bptr + (size_t)(ty * 8 + i) * SS + s0 + tx * 4);
        }
        {
            int s = tid >> 2;
            int dc = (tid & 3) * 16;
            const float* kp = kbase + (size_t)(s0 + s) * DH + dc;
#pragma unroll
            for (int q = 0; q < 4; q++)
                cpa16(ks_u + (uint32_t)((s * W68 + dc + q * 4) * 4), kp + q * 4);
        }
        asm volatile("cp.async.commit_group;" ::: "memory");

        // V: uint4 LDG + transpose STS (tf32 bits, no conversion)
        {
            int s = tid >> 2;
            int dc = (tid & 3) * 16;
            const uint4* vp = (const uint4*)(vbase + (size_t)(s0 + s) * DH + dc);
            uint32_t* Vb = (uint32_t*)Vt;
#pragma unroll
            for (int q = 0; q < 4; q++) {
                uint4 vv = vp[q];
                int d = dc + q * 4;
                Vb[(d + 0) * W68 + s] = vv.x;
                Vb[(d + 1) * W68 + s] = vv.y;
                Vb[(d + 2) * W68 + s] = vv.z;
                Vb[(d + 3) * W68 + s] = vv.w;
            }
        }
        asm volatile("cp.async.wait_group 0;" ::: "memory");
        __syncthreads();

        // S = Q K^T via mma.sync tf32 (warp tile 32m x 32n, K-dim 64)
        float sf[2][4][4];
#pragma unroll
        for (int mt = 0; mt < 2; mt++)
#pragma unroll
            for (int nt = 0; nt < 4; nt++)
#pragma unroll
                for (int r = 0; r < 4; r++) sf[mt][nt][r] = 0.f;
        {
            const uint32_t* Qb = (const uint32_t*)Qs;
            const uint32_t* Kb = (const uint32_t*)Ks;
#pragma unroll
            for (int k8 = 0; k8 < 8; k8++) {
                const int k = k8 * 8 + tg;
                uint32_t af[2][4], bf[4][2];
#pragma unroll
                for (int mt = 0; mt < 2; mt++) {
                    int r = wm * 32 + mt * 16 + g;
                    af[mt][0] = Qb[r * W68 + k];
                    af[mt][1] = Qb[(r + 8) * W68 + k];
                    af[mt][2] = Qb[r * W68 + k + 4];
                    af[mt][3] = Qb[(r + 8) * W68 + k + 4];
                }
#pragma unroll
                for (int nt = 0; nt < 4; nt++) {
                    int n = wn * 32 + nt * 8 + g;
                    bf[nt][0] = Kb[n * W68 + k];
                    bf[nt][1] = Kb[n * W68 + k + 4];
                }
#pragma unroll
                for (int mt = 0; mt < 2; mt++)
#pragma unroll
                    for (int nt = 0; nt < 4; nt++)
                        mma8(sf[mt][nt], af[mt], bf[nt]);
            }
        }

        // bias (prefetched in Ps) + ex2 in fragment layout; write P into Ps
#pragma unroll
        for (int mt = 0; mt < 2; mt++) {
            int r0 = wm * 32 + mt * 16 + g;
#pragma unroll
            for (int nt = 0; nt < 4; nt++) {
                int c = wn * 32 + nt * 8 + 2 * tg;
                float2 b0 = *(float2*)&Ps[r0 * W68 + c];
                float2 b1 = *(float2*)&Ps[(r0 + 8) * W68 + c];
                float p00 = ex2(sf[mt][nt][0] + b0.x - FIXC);
                float p01 = ex2(sf[mt][nt][1] + b0.y - FIXC);
                float p10 = ex2(sf[mt][nt][2] + b1.x - FIXC);
                float p11 = ex2(sf[mt][nt][3] + b1.y - FIXC);
                lsum[mt * 2 + 0] += p00 + p01;
                lsum[mt * 2 + 1] += p10 + p11;
                *(float2*)&Ps[r0 * W68 + c]       = make_float2(p00, p01);
                *(float2*)&Ps[(r0 + 8) * W68 + c] = make_float2(p10, p11);
            }
        }
        __syncthreads();

        // O += P V (mma.sync tf32; P raw fp32, HW-truncated)
        {
            const uint32_t* Pr = (const uint32_t*)Ps;
            const uint32_t* Vr = (const uint32_t*)Vt;
#pragma unroll
            for (int kk = 0; kk < 8; kk++) {
                const int k = kk * 8 + tg;
                uint32_t af[2][4];
#pragma unroll
                for (int mt = 0; mt < 2; mt++) {
                    int r = wm * 32 + mt * 16 + g;
                    af[mt][0] = Pr[r * W68 + k];
                    af[mt][1] = Pr[(r + 8) * W68 + k];
                    af[mt][2] = Pr[r * W68 + k + 4];
                    af[mt][3] = Pr[(r + 8) * W68 + k + 4];
                }
#pragma unroll
                for (int nt = 0; nt < 4; nt++) {
                    int n = wn * 32 + nt * 8 + g;
                    uint32_t bf[2];
                    bf[0] = Vr[n * W68 + k];
                    bf[1] = Vr[n * W68 + k + 4];
                    mma8(o[0][nt], af[0], bf);
                    mma8(o[1][nt], af[1], bf);
                }
            }
        }
    }

    // reduce lsum over the 4-lane tg group; publish per-row, per-wn sums
#pragma unroll
    for (int i = 0; i < 4; i++) {
        lsum[i] += __shfl_xor_sync(0xffffffffu, lsum[i], 1);
        lsum[i] += __shfl_xor_sync(0xffffffffu, lsum[i], 2);
    }
    if (tg == 0) {
#pragma unroll
        for (int mt = 0; mt < 2; mt++) {
            int r = wm * 32 + mt * 16 + g;
            Ls[wn * 128 + r]     = lsum[mt * 2 + 0];
            Ls[wn * 128 + r + 8] = lsum[mt * 2 + 1];
        }
    }
    __syncthreads();

    // epilogue: normalize O and write TF32 BITS to g_vals [B,T,D]
#pragma unroll
    for (int mt = 0; mt < 2; mt++) {
        int r = wm * 32 + mt * 16 + g;
        float inv0 = 1.0f / (Ls[r] + Ls[128 + r]);
        float inv1 = 1.0f / (Ls[r + 8] + Ls[128 + r + 8]);
        uint32_t* d0 = (uint32_t*)(g_vals + ((size_t)(b * TT) + t0 + r) * DM + h * DH);
        uint32_t* d1 = (uint32_t*)(g_vals + ((size_t)(b * TT) + t0 + r + 8) * DM + h * DH);
#pragma unroll
        for (int nt = 0; nt < 4; nt++) {
            int c = wn * 32 + nt * 8 + 2 * tg;
            uint2 u0, u1;
            u0.x = f2tf(o[mt][nt][0] * inv0);
            u0.y = f2tf(o[mt][nt][1] * inv0);
            u1.x = f2tf(o[mt][nt][2] * inv1);
            u1.y = f2tf(o[mt][nt][3] * inv1);
            *(uint2*)(d0 + c) = u0;
            *(uint2*)(d1 + c) = u1;
        }
    }
}

// ---------------------------------------------------------------------------
extern "C" void kernel_launch(void* const* d_in, const int* in_sizes, int n_in,
                              void* d_out, int out_size) {
    const float* q    = (const float*)d_in[0];
    const float* k    = (const float*)d_in[1];
    const float* v    = (const float*)d_in[2];
    const float* bias = (const float*)d_in[3];
    const float* Wqkv = (const float*)d_in[4];
    const float* Wout = (const float*)d_in[5];
    const float* ls   = (const float*)d_in[6];
    float* out = (float*)d_out;

    cudaFuncSetAttribute(attention_kernel,
                         cudaFuncAttributeMaxDynamicSharedMemorySize, ATT_SMEM);
    cudaFuncSetAttribute(fused_pre_kernel,
                         cudaFuncAttributeMaxDynamicSharedMemorySize, PRE_SMEM);
    cudaFuncSetAttribute(gemm_out_kernel,
                         cudaFuncAttributeMaxDynamicSharedMemorySize, PRE_SMEM);

    convert_kernel<<<dim3(4096, 5), 256>>>(q, k, v, Wqkv, Wout);

    fused_pre_kernel<<<dim3(32, 8, 4), 256, PRE_SMEM>>>(bias, ls);

    attention_kernel<<<dim3(TT / 128, NH, BB), 256, ATT_SMEM>>>();

    gemm_out_kernel<<<dim3(32, 8), 256, PRE_SMEM>>>(out);
}

// round 17
// speedup vs baseline: 1.2994x; 1.1102x over previous
#include <cuda_runtime.h>
#include <math.h>
#include <stdint.h>

#define BB 2
#define TT 2048
#define SS 2048
#define DM 1024
#define NH 16
#define DH 64
#define KK 1024

// Scratch (static device globals — allocation-free rule)
// g_qn/g_kn/g_vh/g_vals hold TF32 BIT PATTERNS.
// g_cq/g_ck/g_cv: QUAD layout   [mtile32][chunk64][ks2][blk8][4g+tg 32] x 4 elems
// g_cw:           PAIR layout   [ntile8][chunk64][nb16][ks2][4g+tg 32] x 2 elems
// g_cwo:          linear tf32 bits (out_gemm keeps linear body)
__device__ float g_qn[(size_t)BB*NH*TT*DH];
__device__ float g_kn[(size_t)BB*NH*SS*DH];
__device__ float g_vh[(size_t)BB*NH*SS*DH];
__device__ float g_vals[(size_t)BB*TT*DM];
__device__ float g_biasT[(size_t)NH*TT*SS];    // bias [H,T,S], x log2e (fp32)
__device__ uint32_t g_cq[(size_t)4096*1024];
__device__ uint32_t g_ck[(size_t)4096*1024];
__device__ uint32_t g_cv[(size_t)4096*1024];
__device__ uint32_t g_cw[(size_t)1024*1024];
__device__ uint32_t g_cwo[(size_t)1024*1024];

#define LOG2E 1.4426950408889634f
#define FIXC 24.0f

// ---------------- helpers ----------------
__device__ __forceinline__ uint32_t f2tf(float f) {
    uint32_t r; asm("cvt.rna.tf32.f32 %0, %1;" : "=r"(r) : "f"(f)); return r;
}
__device__ __forceinline__ float ex2(float x) {
    float r; asm("ex2.approx.ftz.f32 %0, %1;" : "=f"(r) : "f"(x)); return r;
}
__device__ __forceinline__ void mma8(float* d, const uint32_t* a, const uint32_t* b) {
    asm("mma.sync.aligned.m16n8k8.row.col.f32.tf32.tf32.f32 "
        "{%0,%1,%2,%3}, {%4,%5,%6,%7}, {%8,%9}, {%0,%1,%2,%3};"
        : "+f"(d[0]), "+f"(d[1]), "+f"(d[2]), "+f"(d[3])
        : "r"(a[0]), "r"(a[1]), "r"(a[2]), "r"(a[3]), "r"(b[0]), "r"(b[1]));
}
__device__ __forceinline__ uint32_t s2u(const void* p) {
    uint32_t a;
    asm("{ .reg .u64 t; cvta.to.shared.u64 t, %1; cvt.u32.u64 %0, t; }"
        : "=r"(a) : "l"(p));
    return a;
}
__device__ __forceinline__ void cpa16(uint32_t dst, const void* src) {
    asm volatile("cp.async.cg.shared.global [%0], [%1], 16;"
                 :: "r"(dst), "l"(src) : "memory");
}

// ---------------------------------------------------------------------------
// Convert inputs to tf32 bits in mma-fragment-friendly layouts.
// z=0..2: q/k/v -> quads. z=3: Wqkv -> pairs. z=4: Wout -> linear.
// ---------------------------------------------------------------------------
__global__ __launch_bounds__(256) void convert_kernel(const float* __restrict__ q,
                                                      const float* __restrict__ k,
                                                      const float* __restrict__ v,
                                                      const float* __restrict__ wqkv,
                                                      const float* __restrict__ wout) {
    const int z = blockIdx.y;
    const uint32_t F = blockIdx.x * 256 + threadIdx.x;
    if (z < 3) {
        const float* src = (z == 0) ? q : (z == 1) ? k : v;
        uint32_t* dst = (z == 0) ? g_cq : (z == 1) ? g_ck : g_cv;
        // F < 1M (grid.x = 4096)
        uint32_t mc = F >> 9;             // mtile*64 + chunk
        uint32_t qd = F & 511;
        uint32_t mtile = mc >> 6, chunk = mc & 63;
        uint32_t ks = qd >> 8, blk = (qd >> 5) & 7, low = qd & 31;
        uint32_t g = low >> 2, tg = low & 3;
        size_t r0 = (size_t)mtile * 128 + blk * 16 + g;
        size_t c0 = (size_t)chunk * 16 + ks * 8 + tg;
        const float* s = src + r0 * KK + c0;
        uint4 u;
        u.x = f2tf(s[0]);
        u.y = f2tf(s[(size_t)8 * KK]);
        u.z = f2tf(s[4]);
        u.w = f2tf(s[(size_t)8 * KK + 4]);
        *(uint4*)(dst + (size_t)F * 4) = u;
    } else if (z == 3) {
        if (F >= 512u * 1024u) return;
        uint32_t nc = F >> 10;            // ntile*64 + chunk
        uint32_t p = F & 1023;
        uint32_t ntile = nc >> 6, chunk = nc & 63;
        uint32_t nb = p >> 6, ks = (p >> 5) & 1, low = p & 31;
        uint32_t g = low >> 2, tg = low & 3;
        size_t n0 = (size_t)ntile * 128 + nb * 8 + g;
        size_t c0 = (size_t)chunk * 16 + ks * 8 + tg;
        const float* s = wqkv + n0 * KK + c0;
        uint2 u;
        u.x = f2tf(s[0]);
        u.y = f2tf(s[4]);
        *(uint2*)(g_cw + (size_t)F * 2) = u;
    } else {
        if (F >= 256u * 1024u) return;
        size_t i = (size_t)F * 4;
        float4 vv = *(const float4*)(wout + i);
        uint4 u;
        u.x = f2tf(vv.x); u.y = f2tf(vv.y); u.z = f2tf(vv.z); u.w = f2tf(vv.w);
        *(uint4*)(g_cwo + i) = u;
    }
}

// ---------------------------------------------------------------------------
// Projection GEMM body: quad/pair fragment layout, all-cp.async 3-stage pipe.
// CTA 128x128, BK=16, 8 warps (2x4). Vector fragment loads (LDS.128/LDS.64).
// mode 1/2/3: TF32 BITS -> g_vh/g_kn/g_qn (+norm/scale for 2/3).
// ---------------------------------------------------------------------------
#define QSTG 2048                        // u32 per operand-stage (8KB)
#define PRE_FLOATS (128 * 132)
#define PRE_SMEM (PRE_FLOATS * (int)sizeof(float))

__device__ __forceinline__ void gemm_quad_body(const uint32_t* __restrict__ Aq,
                                               const uint32_t* __restrict__ Wp,
                                               const float* __restrict__ ls,
                                               int mode, float* sm) {
    float* Cs = sm;
    const int tid = threadIdx.x;
    const int wid = tid >> 5, lane = tid & 31;
    const int wm = wid >> 2, wn = wid & 3;
    const int g = lane >> 2, tg = lane & 3;
    const uint32_t sm_u = s2u(sm);

    const uint32_t* aP = Aq + ((size_t)blockIdx.x * 64) * 2048 + tid * 8;
    const uint32_t* wP = Wp + ((size_t)blockIdx.y * 64) * 2048 + tid * 8;
    const uint32_t a_dst = sm_u + (uint32_t)(tid * 32);
    const uint32_t b_dst = sm_u + (uint32_t)(3 * QSTG * 4) + (uint32_t)(tid * 32);

    float d[4][4][4];
#pragma unroll
    for (int mt = 0; mt < 4; mt++)
#pragma unroll
        for (int nt = 0; nt < 4; nt++)
#pragma unroll
            for (int r = 0; r < 4; r++) d[mt][nt][r] = 0.f;

#define Q_ISSUE(c) do {                                                  \
        const int st_ = (c) % 3;                                         \
        cpa16(a_dst + (uint32_t)(st_ * QSTG * 4), aP + (size_t)(c) * 2048);     \
        cpa16(a_dst + (uint32_t)(st_ * QSTG * 4) + 16, aP + (size_t)(c) * 2048 + 4); \
        cpa16(b_dst + (uint32_t)(st_ * QSTG * 4), wP + (size_t)(c) * 2048);     \
        cpa16(b_dst + (uint32_t)(st_ * QSTG * 4) + 16, wP + (size_t)(c) * 2048 + 4); \
        asm volatile("cp.async.commit_group;" ::: "memory");             \
    } while (0)

    const int NC = KK / 16;
    Q_ISSUE(0);
    Q_ISSUE(1);

    for (int c = 0; c < NC; c++) {
        if (c + 1 < NC)
            asm volatile("cp.async.wait_group 1;" ::: "memory");
        else
            asm volatile("cp.async.wait_group 0;" ::: "memory");
        __syncthreads();
        if (c + 2 < NC) Q_ISSUE(c + 2);

        const uint32_t* Ab = (const uint32_t*)sm + (c % 3) * QSTG;
        const uint32_t* Bb = (const uint32_t*)sm + 3 * QSTG + (c % 3) * QSTG;
#pragma unroll
        for (int ks = 0; ks < 2; ks++) {
            uint4 af[4];
            uint2 bf[4];
#pragma unroll
            for (int mt = 0; mt < 4; mt++)
                af[mt] = *(const uint4*)(Ab + ((ks * 8 + wm * 4 + mt) * 32 + 4 * g + tg) * 4);
#pragma unroll
            for (int nt = 0; nt < 4; nt++)
                bf[nt] = *(const uint2*)(Bb + (((wn * 4 + nt) * 2 + ks) * 32 + 4 * g + tg) * 2);
#pragma unroll
            for (int mt = 0; mt < 4; mt++)
#pragma unroll
                for (int nt = 0; nt < 4; nt++)
                    mma8(d[mt][nt], (const uint32_t*)&af[mt], (const uint32_t*)&bf[nt]);
        }
    }
    __syncthreads();

#pragma unroll
    for (int mt = 0; mt < 4; mt++) {
        int r = wm * 64 + mt * 16 + g;
#pragma unroll
        for (int nt = 0; nt < 4; nt++) {
            int cc = wn * 32 + nt * 8 + 2 * tg;
            *(float2*)&Cs[r * 132 + cc]       = make_float2(d[mt][nt][0], d[mt][nt][1]);
            *(float2*)&Cs[(r + 8) * 132 + cc] = make_float2(d[mt][nt][2], d[mt][nt][3]);
        }
    }
    __syncthreads();

    {
        const int row = tid >> 1;
        const int half = tid & 1;
        float f[64];
        const float* src = &Cs[row * 132 + half * 64];
#pragma unroll
        for (int j = 0; j < 16; j++) {
            float4 v = *(const float4*)(src + j * 4);
            f[4 * j] = v.x; f[4 * j + 1] = v.y; f[4 * j + 2] = v.z; f[4 * j + 3] = v.w;
        }
        if (mode >= 2) {
            float ssq = 0.f;
#pragma unroll
            for (int j = 0; j < 64; j++) ssq += f[j] * f[j];
            float hs = 1.0f;
            if (mode == 3)
                hs = expf(fminf(ls[blockIdx.y * 2 + half], 4.6051701859880914f)) * LOG2E;
            float inv = hs / fmaxf(sqrtf(ssq), 1e-12f);
#pragma unroll
            for (int j = 0; j < 64; j++) f[j] *= inv;
        }
        const int m = blockIdx.x * 128 + row;
        int b = m >> 11, t = m & 2047;
        int h = ((int)blockIdx.y * 128 >> 6) + half;
        float* base = (mode == 1) ? g_vh : (mode == 2) ? g_kn : g_qn;
        uint32_t* dst = (uint32_t*)(base + (((size_t)(b * NH + h)) * TT + t) * DH);
#pragma unroll
        for (int j = 0; j < 16; j++) {
            uint4 u;
            u.x = f2tf(f[4 * j]);
            u.y = f2tf(f[4 * j + 1]);
            u.z = f2tf(f[4 * j + 2]);
            u.w = f2tf(f[4 * j + 3]);
            *(uint4*)(dst + j * 4) = u;
        }
    }
}

// ---------------------------------------------------------------------------
// Output GEMM body (R16 linear layout, cp.async pipeline): out = g_vals @ Wout^T
// ---------------------------------------------------------------------------
#define LDK 20
#define STGF (128 * LDK)

__global__ __launch_bounds__(256, 2) void gemm_out_kernel(float* __restrict__ out) {
    extern __shared__ float sm[];
    float* Cs = sm;
    const uint32_t* Abits = (const uint32_t*)g_vals;
    const uint32_t* Wbits = g_cwo;
    const int m0 = blockIdx.x * 128;
    const int n0 = blockIdx.y * 128;
    const int tid = threadIdx.x;
    const int wid = tid >> 5, lane = tid & 31;
    const int wm = wid >> 2, wn = wid & 3;
    const int g = lane >> 2, tg = lane & 3;

    const uint32_t sm_u = s2u(sm);
    const int srow = tid >> 1;
    const int skc = (tid & 1) * 8;
    const uint32_t* aP = Abits + (size_t)(m0 + srow) * KK + skc;
    const uint32_t* wP = Wbits + (size_t)(n0 + srow) * KK + skc;
    const uint32_t a_dst = sm_u + (uint32_t)((srow * LDK + skc) * 4);
    const uint32_t b_dst = sm_u + (uint32_t)(3 * STGF * 4) +
                           (uint32_t)((srow * LDK + skc) * 4);

    float d[4][4][4];
#pragma unroll
    for (int mt = 0; mt < 4; mt++)
#pragma unroll
        for (int nt = 0; nt < 4; nt++)
#pragma unroll
            for (int r = 0; r < 4; r++) d[mt][nt][r] = 0.f;

#define G_ISSUE(c) do {                                            \
        const int st_ = (c) % 3;                                   \
        cpa16(a_dst + (uint32_t)(st_ * STGF * 4), aP + (c) * 16);       \
        cpa16(a_dst + (uint32_t)(st_ * STGF * 4) + 16, aP + (c) * 16 + 4); \
        cpa16(b_dst + (uint32_t)(st_ * STGF * 4), wP + (c) * 16);       \
        cpa16(b_dst + (uint32_t)(st_ * STGF * 4) + 16, wP + (c) * 16 + 4); \
        asm volatile("cp.async.commit_group;" ::: "memory");       \
    } while (0)

    const int NC = KK / 16;
    G_ISSUE(0);
    G_ISSUE(1);

    for (int c = 0; c < NC; c++) {
        if (c + 1 < NC)
            asm volatile("cp.async.wait_group 1;" ::: "memory");
        else
            asm volatile("cp.async.wait_group 0;" ::: "memory");
        __syncthreads();
        if (c + 2 < NC) G_ISSUE(c + 2);

        const uint32_t* Ab = (const uint32_t*)sm + (c % 3) * STGF;
        const uint32_t* Bb = (const uint32_t*)sm + 3 * STGF + (c % 3) * STGF;
#pragma unroll
        for (int ks = 0; ks < 2; ks++) {
            const int k = ks * 8 + tg;
            uint32_t af[4][4], bf[4][2];
#pragma unroll
            for (int mt = 0; mt < 4; mt++) {
                int r = wm * 64 + mt * 16 + g;
                af[mt][0] = Ab[r * LDK + k];
                af[mt][1] = Ab[(r + 8) * LDK + k];
                af[mt][2] = Ab[r * LDK + k + 4];
                af[mt][3] = Ab[(r + 8) * LDK + k + 4];
            }
#pragma unroll
            for (int nt = 0; nt < 4; nt++) {
                int n = wn * 32 + nt * 8 + g;
                bf[nt][0] = Bb[n * LDK + k];
                bf[nt][1] = Bb[n * LDK + k + 4];
            }
#pragma unroll
            for (int mt = 0; mt < 4; mt++)
#pragma unroll
                for (int nt = 0; nt < 4; nt++)
                    mma8(d[mt][nt], af[mt], bf[nt]);
        }
    }
    __syncthreads();

#pragma unroll
    for (int mt = 0; mt < 4; mt++) {
        int r = wm * 64 + mt * 16 + g;
#pragma unroll
        for (int nt = 0; nt < 4; nt++) {
            int cc = wn * 32 + nt * 8 + 2 * tg;
            *(float2*)&Cs[r * 132 + cc]       = make_float2(d[mt][nt][0], d[mt][nt][1]);
            *(float2*)&Cs[(r + 8) * 132 + cc] = make_float2(d[mt][nt][2], d[mt][nt][3]);
        }
    }
    __syncthreads();

    {
        const int row = tid >> 1;
        const int half = tid & 1;
        const float* src = &Cs[row * 132 + half * 64];
        float* dst = out + (size_t)(m0 + row) * DM + n0 + half * 64;
#pragma unroll
        for (int j = 0; j < 16; j++)
            *(float4*)(dst + j * 4) = *(const float4*)(src + j * 4);
    }
}

// ---------------------------------------------------------------------------
// Bias transpose: [T,S,H] -> [H,T,S], scaled by log2e.
// ---------------------------------------------------------------------------
__device__ __forceinline__ void transpose_body(const float* __restrict__ in, float* sm) {
    const int c = blockIdx.y * 32 + blockIdx.x;
    const int tid = threadIdx.x;
    for (int tb = 0; tb < 2; tb++) {
        const int t0 = (c * 2 + tb) * 4;
        for (int s0 = 0; s0 < SS; s0 += 64) {
#pragma unroll
            for (int tt = 0; tt < 4; tt++) {
                const float* src = in + ((size_t)(t0 + tt) * SS + s0) * NH;
#pragma unroll
                for (int p = 0; p < 4; p++) {
                    int idx = p * 256 + tid;
                    int h = idx & 15, ss = idx >> 4;
                    sm[h * 261 + tt * 64 + ss] = src[idx] * LOG2E;
                }
            }
            __syncthreads();
#pragma unroll
            for (int p = 0; p < 16; p++) {
                int idx = p * 256 + tid;
                int ss = idx & 63;
                int combo = idx >> 6;
                int tt = combo & 3, h = combo >> 2;
                g_biasT[(size_t)h * TT * SS + (size_t)(t0 + tt) * SS + s0 + ss] =
                    sm[h * 261 + tt * 64 + ss];
            }
            __syncthreads();
        }
    }
}

__global__ __launch_bounds__(256, 2) void fused_pre_kernel(const float* __restrict__ bias,
                                                           const float* __restrict__ ls) {
    extern __shared__ float sm[];
    const int z = blockIdx.z;
    if (z == 0)      gemm_quad_body(g_cq, g_cw, ls, 3, sm);
    else if (z == 1) gemm_quad_body(g_ck, g_cw, nullptr, 2, sm);
    else if (z == 2) gemm_quad_body(g_cv, g_cw, nullptr, 1, sm);
    else             transpose_body(bias, sm);
}

// ---------------------------------------------------------------------------
// Flash attention: BM=128(t), BN=64(s), 256 thr, all-tensor.
// V STS column-swizzled (conflict-free). K(s+1) issued right after the post-P
// barrier so its load overlaps PV + V staging.
// Smem: Qs[128][68] | Ks[64][68] | Vt[64][68] | Ps[128][68] | Ls[2][128].
// ---------------------------------------------------------------------------
#define W68 68
#define ATT_FLOATS (128*W68 + 64*W68 + 64*W68 + 128*W68 + 256)
#define ATT_SMEM (ATT_FLOATS * (int)sizeof(float))

__global__ __launch_bounds__(256, 2) void attention_kernel() {
    extern __shared__ float sm[];
    float* Qs = sm;                         // [128][68] tf32 bits
    float* Ks = sm + 128 * W68;             // [64][68] tf32 bits
    float* Vt = Ks + 64 * W68;              // [64][68] tf32 bits, col-swizzled
    float* Ps = Vt + 64 * W68;              // [128][68]  (bias, then P)
    float* Ls = Ps + 128 * W68;             // [2][128]

    const int t0 = blockIdx.x * 128;
    const int h = blockIdx.y;
    const int b = blockIdx.z;
    const int tid = threadIdx.x;
    const int tx = tid & 15, ty = tid >> 4;
    const int wid = tid >> 5, lane = tid & 31;
    const int g = lane >> 2, tg = lane & 3;
    const int wm = wid >> 1, wn = wid & 1;

    const uint32_t qs_u = s2u(Qs);
    const uint32_t ks_u = s2u(Ks);
    const uint32_t ps_u = s2u(Ps);

    const float* qptr  = g_qn + (((size_t)(b * NH + h)) * TT + t0) * DH;
    const float* kbase = g_kn + ((size_t)(b * NH + h)) * SS * DH;
    const float* vbase = g_vh + ((size_t)(b * NH + h)) * SS * DH;
    const float* bptr  = g_biasT + (size_t)h * TT * SS + (size_t)t0 * SS;

    // per-thread staging coords
    const int svs = tid >> 2;
    const int svd = (tid & 3) * 16;
    const int soff = (tid & 3) * 8;          // V column swizzle = 8*(d>>4)
    // PV reader V-column offsets (warp-uniform per nt)
    int voff[4];
#pragma unroll
    for (int nt = 0; nt < 4; nt++)
        voff[nt] = (((wn * 32 + nt * 8 + g) >> 4) & 3) * 8;

    // Stage Q tile once via cp.async
    {
        int row = tid >> 1;
        int dc0 = (tid & 1) * 32;
        const float* qp = qptr + (size_t)row * DH + dc0;
#pragma unroll
        for (int j = 0; j < 8; j++)
            cpa16(qs_u + (uint32_t)((row * W68 + dc0 + j * 4) * 4), qp + j * 4);
        asm volatile("cp.async.commit_group;" ::: "memory");
    }
    // issue K tile 0
    {
        const float* kp = kbase + (size_t)svs * DH + svd;
#pragma unroll
        for (int q = 0; q < 4; q++)
            cpa16(ks_u + (uint32_t)((svs * W68 + svd + q * 4) * 4), kp + q * 4);
        asm volatile("cp.async.commit_group;" ::: "memory");
    }

    float lsum[4] = {0.f, 0.f, 0.f, 0.f};
    float o[2][4][4];
#pragma unroll
    for (int mt = 0; mt < 2; mt++)
#pragma unroll
        for (int nt = 0; nt < 4; nt++)
#pragma unroll
            for (int r = 0; r < 4; r++) o[mt][nt][r] = 0.f;

    for (int s0 = 0; s0 < SS; s0 += 64) {
        __syncthreads();   // Vt/Ps free (prev PV done)

        // bias cp.async into Ps
#pragma unroll
        for (int i = 0; i < 8; i++) {
            cpa16(ps_u + (uint32_t)(((ty * 8 + i) * W68 + tx * 4) * 4),
                  bptr + (size_t)(ty * 8 + i) * SS + s0 + tx * 4);
        }
        asm volatile("cp.async.commit_group;" ::: "memory");

        // V: uint4 LDG + swizzled transpose STS (conflict-free)
        {
            const uint4* vp = (const uint4*)(vbase + (size_t)(s0 + svs) * DH + svd);
            uint32_t* Vb = (uint32_t*)Vt;
            const int sc = (svs + soff) & 63;
#pragma unroll
            for (int q = 0; q < 4; q++) {
                uint4 vv = vp[q];
                int d = svd + q * 4;
                Vb[(d + 0) * W68 + sc] = vv.x;
                Vb[(d + 1) * W68 + sc] = vv.y;
                Vb[(d + 2) * W68 + sc] = vv.z;
                Vb[(d + 3) * W68 + sc] = vv.w;
            }
        }
        asm volatile("cp.async.wait_group 0;" ::: "memory");
        __syncthreads();

        // S = Q K^T via mma.sync tf32
        float sf[2][4][4];
#pragma unroll
        for (int mt = 0; mt < 2; mt++)
#pragma unroll
            for (int nt = 0; nt < 4; nt++)
#pragma unroll
                for (int r = 0; r < 4; r++) sf[mt][nt][r] = 0.f;
        {
            const uint32_t* Qb = (const uint32_t*)Qs;
            const uint32_t* Kb = (const uint32_t*)Ks;
#pragma unroll
            for (int k8 = 0; k8 < 8; k8++) {
                const int k = k8 * 8 + tg;
                uint32_t af[2][4], bf[4][2];
#pragma unroll
                for (int mt = 0; mt < 2; mt++) {
                    int r = wm * 32 + mt * 16 + g;
                    af[mt][0] = Qb[r * W68 + k];
                    af[mt][1] = Qb[(r + 8) * W68 + k];
                    af[mt][2] = Qb[r * W68 + k + 4];
                    af[mt][3] = Qb[(r + 8) * W68 + k + 4];
                }
#pragma unroll
                for (int nt = 0; nt < 4; nt++) {
                    int n = wn * 32 + nt * 8 + g;
                    bf[nt][0] = Kb[n * W68 + k];
                    bf[nt][1] = Kb[n * W68 + k + 4];
                }
#pragma unroll
                for (int mt = 0; mt < 2; mt++)
#pragma unroll
                    for (int nt = 0; nt < 4; nt++)
                        mma8(sf[mt][nt], af[mt], bf[nt]);
            }
        }

        // bias + ex2 in fragment layout; write P into Ps
#pragma unroll
        for (int mt = 0; mt < 2; mt++) {
            int r0 = wm * 32 + mt * 16 + g;
#pragma unroll
            for (int nt = 0; nt < 4; nt++) {
                int c = wn * 32 + nt * 8 + 2 * tg;
                float2 b0 = *(float2*)&Ps[r0 * W68 + c];
                float2 b1 = *(float2*)&Ps[(r0 + 8) * W68 + c];
                float p00 = ex2(sf[mt][nt][0] + b0.x - FIXC);
                float p01 = ex2(sf[mt][nt][1] + b0.y - FIXC);
                float p10 = ex2(sf[mt][nt][2] + b1.x - FIXC);
                float p11 = ex2(sf[mt][nt][3] + b1.y - FIXC);
                lsum[mt * 2 + 0] += p00 + p01;
                lsum[mt * 2 + 1] += p10 + p11;
                *(float2*)&Ps[r0 * W68 + c]       = make_float2(p00, p01);
                *(float2*)&Ps[(r0 + 8) * W68 + c] = make_float2(p10, p11);
            }
        }
        __syncthreads();   // P visible; all QK readers of Ks done

        // issue K(s+1) now — overlaps PV + next V staging
        if (s0 + 64 < SS) {
            const float* kp = kbase + (size_t)(s0 + 64 + svs) * DH + svd;
#pragma unroll
            for (int q = 0; q < 4; q++)
                cpa16(ks_u + (uint32_t)((svs * W68 + svd + q * 4) * 4), kp + q * 4);
            asm volatile("cp.async.commit_group;" ::: "memory");
        }

        // O += P V (V columns swizzled)
        {
            const uint32_t* Pr = (const uint32_t*)Ps;
            const uint32_t* Vr = (const uint32_t*)Vt;
#pragma unroll
            for (int kk = 0; kk < 8; kk++) {
                const int k = kk * 8 + tg;
                uint32_t af[2][4];
#pragma unroll
                for (int mt = 0; mt < 2; mt++) {
                    int r = wm * 32 + mt * 16 + g;
                    af[mt][0] = Pr[r * W68 + k];
                    af[mt][1] = Pr[(r + 8) * W68 + k];
                    af[mt][2] = Pr[r * W68 + k + 4];
                    af[mt][3] = Pr[(r + 8) * W68 + k + 4];
                }
#pragma unroll
                for (int nt = 0; nt < 4; nt++) {
                    int n = wn * 32 + nt * 8 + g;
                    uint32_t bf[2];
                    bf[0] = Vr[n * W68 + ((k + voff[nt]) & 63)];
                    bf[1] = Vr[n * W68 + ((k + 4 + voff[nt]) & 63)];
                    mma8(o[0][nt], af[0], bf);
                    mma8(o[1][nt], af[1], bf);
                }
            }
        }
    }

    // reduce lsum over the 4-lane tg group; publish per-row, per-wn sums
#pragma unroll
    for (int i = 0; i < 4; i++) {
        lsum[i] += __shfl_xor_sync(0xffffffffu, lsum[i], 1);
        lsum[i] += __shfl_xor_sync(0xffffffffu, lsum[i], 2);
    }
    if (tg == 0) {
#pragma unroll
        for (int mt = 0; mt < 2; mt++) {
            int r = wm * 32 + mt * 16 + g;
            Ls[wn * 128 + r]     = lsum[mt * 2 + 0];
            Ls[wn * 128 + r + 8] = lsum[mt * 2 + 1];
        }
    }
    __syncthreads();

    // epilogue: normalize O and write TF32 BITS to g_vals [B,T,D]
#pragma unroll
    for (int mt = 0; mt < 2; mt++) {
        int r = wm * 32 + mt * 16 + g;
        float inv0 = 1.0f / (Ls[r] + Ls[128 + r]);
        float inv1 = 1.0f / (Ls[r + 8] + Ls[128 + r + 8]);
        uint32_t* d0 = (uint32_t*)(g_vals + ((size_t)(b * TT) + t0 + r) * DM + h * DH);
        uint32_t* d1 = (uint32_t*)(g_vals + ((size_t)(b * TT) + t0 + r + 8) * DM + h * DH);
#pragma unroll
        for (int nt = 0; nt < 4; nt++) {
            int c = wn * 32 + nt * 8 + 2 * tg;
            uint2 u0, u1;
            u0.x = f2tf(o[mt][nt][0] * inv0);
            u0.y = f2tf(o[mt][nt][1] * inv0);
            u1.x = f2tf(o[mt][nt][2] * inv1);
            u1.y = f2tf(o[mt][nt][3] * inv1);
            *(uint2*)(d0 + c) = u0;
            *(uint2*)(d1 + c) = u1;
        }
    }
}

// ---------------------------------------------------------------------------
extern "C" void kernel_launch(void* const* d_in, const int* in_sizes, int n_in,
                              void* d_out, int out_size) {
    const float* q    = (const float*)d_in[0];
    const float* k    = (const float*)d_in[1];
    const float* v    = (const float*)d_in[2];
    const float* bias = (const float*)d_in[3];
    const float* Wqkv = (const float*)d_in[4];
    const float* Wout = (const float*)d_in[5];
    const float* ls   = (const float*)d_in[6];
    float* out = (float*)d_out;

    cudaFuncSetAttribute(attention_kernel,
                         cudaFuncAttributeMaxDynamicSharedMemorySize, ATT_SMEM);
    cudaFuncSetAttribute(fused_pre_kernel,
                         cudaFuncAttributeMaxDynamicSharedMemorySize, PRE_SMEM);
    cudaFuncSetAttribute(gemm_out_kernel,
                         cudaFuncAttributeMaxDynamicSharedMemorySize, PRE_SMEM);

    convert_kernel<<<dim3(4096, 5), 256>>>(q, k, v, Wqkv, Wout);

    fused_pre_kernel<<<dim3(32, 8, 4), 256, PRE_SMEM>>>(bias, ls);

    attention_kernel<<<dim3(TT / 128, NH, BB), 256, ATT_SMEM>>>();

    gemm_out_kernel<<<dim3(32, 8), 256, PRE_SMEM>>>(out);
}